// round 2
// baseline (speedup 1.0000x reference)
#include <cuda_runtime.h>
#include <cuda_bf16.h>
#include <mma.h>
#include <cfloat>

using namespace nvcuda;

#define BB 4
#define NN 8192
#define IND 1024
#define HID 512
#define NHEAD 8
#define TOPK 16
#define NCLS 2
#define HH 91
#define PP (HH*HH)      // 8281
#define NP (PP+1)       // 8282 attention rows (cls + conv out)
#define MM (BB*NN)      // 32768

// ---------------- scratch (static __device__, no allocation) ----------------
__device__ __nv_bfloat16 g_in_bf[(size_t)MM*IND];   // 64 MB
__device__ __nv_bfloat16 g_W_bf[IND*HID];           // 1 MB
__device__ float g_venc[IND];
__device__ float g_scores[MM];
__device__ int   g_topk[BB*TOPK];
__device__ float g_suminp[BB*IND];
__device__ float g_Q[BB*HID];
__device__ float g_x[(size_t)MM*HID];               // relu(x - Q), 64 MB
__device__ float g_x2[(size_t)BB*NP*HID];           // cls + conv-out, 66 MB
__device__ float g_qvec[BB*HID];
__device__ float g_u[BB*NHEAD*HID];
__device__ float g_qbk[BB*NHEAD];
__device__ float g_logits[BB*NHEAD*NP];
__device__ float g_mx[BB*NHEAD];
__device__ float g_sm[BB*NHEAD];
__device__ float g_w[BB*NHEAD*HID];

// ---------------- v_enc = W_feat @ w_enc (fp32, exact scores path) ----------
__global__ void k_venc(const float* __restrict__ Wf, const float* __restrict__ wenc) {
    __shared__ float we[HID];
    int tid = threadIdx.x;
    for (int i = tid; i < HID; i += 256) we[i] = wenc[i];
    __syncthreads();
    int warp = tid >> 5, lane = tid & 31;
    int row = blockIdx.x * 8 + warp;
    const float4* r4 = (const float4*)(Wf + (size_t)row*HID);
    float acc = 0.f;
#pragma unroll
    for (int t = 0; t < 4; t++) {
        float4 f = r4[lane + t*32];
        int c = (lane + t*32)*4;
        acc += f.x*we[c] + f.y*we[c+1] + f.z*we[c+2] + f.w*we[c+3];
    }
    for (int o = 16; o; o >>= 1) acc += __shfl_xor_sync(0xffffffffu, acc, o);
    if (lane == 0) g_venc[row] = acc;
}

// ---------------- W_feat -> bf16 --------------------------------------------
__global__ void k_wbf(const float* __restrict__ Wf) {
    int i = blockIdx.x*blockDim.x + threadIdx.x;   // float4 index
    float4 f = ((const float4*)Wf)[i];
    __nv_bfloat162 lo = __floats2bfloat162_rn(f.x, f.y);
    __nv_bfloat162 hi = __floats2bfloat162_rn(f.z, f.w);
    uint2 u;
    u.x = *reinterpret_cast<unsigned*>(&lo);
    u.y = *reinterpret_cast<unsigned*>(&hi);
    ((uint2*)g_W_bf)[i] = u;
}

// ---------------- scores (fp32 GEMV) + inputs -> bf16, one pass -------------
__global__ void k_scores(const float* __restrict__ inp) {
    __shared__ float ve[IND];
    int tid = threadIdx.x;
    for (int i = tid; i < IND; i += 256) ve[i] = g_venc[i];
    __syncthreads();
    int warp = tid >> 5, lane = tid & 31;
    int row = blockIdx.x * 8 + warp;
    const float4* r4 = (const float4*)(inp + (size_t)row*IND);
    uint2* dst = (uint2*)(g_in_bf + (size_t)row*IND);
    float acc = 0.f;
#pragma unroll
    for (int t = 0; t < 8; t++) {
        int i = lane + t*32;
        float4 f = r4[i];
        int c = i*4;
        acc += f.x*ve[c] + f.y*ve[c+1] + f.z*ve[c+2] + f.w*ve[c+3];
        __nv_bfloat162 lo = __floats2bfloat162_rn(f.x, f.y);
        __nv_bfloat162 hi = __floats2bfloat162_rn(f.z, f.w);
        uint2 u;
        u.x = *reinterpret_cast<unsigned*>(&lo);
        u.y = *reinterpret_cast<unsigned*>(&hi);
        dst[i] = u;
    }
    for (int o = 16; o; o >>= 1) acc += __shfl_xor_sync(0xffffffffu, acc, o);
    if (lane == 0) g_scores[row] = acc;
}

// ---------------- top-16 per batch (warp-shuffle argmax iterations) ---------
__global__ void k_topk() {
    __shared__ float sv[NN];
    __shared__ float wv[32];
    __shared__ int   wi[32];
    int b = blockIdx.x, tid = threadIdx.x;
    int lane = tid & 31, warp = tid >> 5;
    for (int i = tid; i < NN; i += 1024) sv[i] = g_scores[b*NN + i];
    __syncthreads();
    for (int k = 0; k < TOPK; k++) {
        float bv = -FLT_MAX; int bi = 0x7fffffff;
#pragma unroll
        for (int t = 0; t < 8; t++) {
            int i = tid + t*1024;
            float v = sv[i];
            if (v > bv || (v == bv && i < bi)) { bv = v; bi = i; }
        }
#pragma unroll
        for (int o = 16; o; o >>= 1) {
            float ov = __shfl_xor_sync(0xffffffffu, bv, o);
            int   oi = __shfl_xor_sync(0xffffffffu, bi, o);
            if (ov > bv || (ov == bv && oi < bi)) { bv = ov; bi = oi; }
        }
        if (lane == 0) { wv[warp] = bv; wi[warp] = bi; }
        __syncthreads();
        if (warp == 0) {
            float v2 = wv[lane]; int i2 = wi[lane];
#pragma unroll
            for (int o = 16; o; o >>= 1) {
                float ov = __shfl_xor_sync(0xffffffffu, v2, o);
                int   oi = __shfl_xor_sync(0xffffffffu, i2, o);
                if (ov > v2 || (ov == v2 && oi < i2)) { v2 = ov; i2 = oi; }
            }
            if (lane == 0) { g_topk[b*TOPK + k] = i2; sv[i2] = -FLT_MAX; }
        }
        __syncthreads();
    }
}

// ---------------- sum of top-k input rows (fp32) ----------------------------
__global__ void k_suminp(const float* __restrict__ inp) {
    int b = blockIdx.x, tid = threadIdx.x;  // 1024 threads
    float acc = 0.f;
#pragma unroll
    for (int k = 0; k < TOPK; k++) {
        int r = g_topk[b*TOPK + k];
        acc += inp[((size_t)b*NN + r)*IND + tid];
    }
    g_suminp[b*IND + tid] = acc;
}

// ---------------- Q = suminp @ W_feat / 16 + b_feat (fp32 exact) ------------
__global__ void k_Q(const float* __restrict__ Wf, const float* __restrict__ bfeat) {
    __shared__ float s[IND];
    int b = blockIdx.x, tid = threadIdx.x;  // 512 threads
    for (int i = tid; i < IND; i += 512) s[i] = g_suminp[b*IND + i];
    __syncthreads();
    float acc = 0.f;
    for (int i = 0; i < IND; i++) acc += s[i]*Wf[(size_t)i*HID + tid];
    g_Q[b*HID + tid] = acc * (1.f/TOPK) + bfeat[tid];
}

// ---------------- main GEMM: 128x128x32, 3-stage cp.async, fused epilogue ---
#define GBM 128
#define GBN 128
#define GBK 32
#define LDA 40
#define LDB 136
#define LDC 132
#define GSTAGES 3
#define A_STAGE (GBM*LDA)         // bf16 elems per A stage
#define B_STAGE (GBK*LDB)         // bf16 elems per B stage
#define GEMM_SMEM (GBM*LDC*4)     // 67584 bytes (C staging dominates)

__device__ __forceinline__ void cp16(void* s, const void* g) {
    unsigned saddr = (unsigned)__cvta_generic_to_shared(s);
    asm volatile("cp.async.cg.shared.global [%0], [%1], 16;\n" :: "r"(saddr), "l"(g));
}

__global__ __launch_bounds__(256) void k_gemm(const float* __restrict__ bfeat) {
    extern __shared__ unsigned char dyn[];
    __nv_bfloat16* Asm = (__nv_bfloat16*)dyn;                        // [3][128][40]
    __nv_bfloat16* Bsm = (__nv_bfloat16*)(dyn + GSTAGES*A_STAGE*2);  // [3][32][136]
    float* Cs = (float*)dyn;                                         // [128][132]

    int tid = threadIdx.x;
    int m0 = blockIdx.y * GBM;
    int n0 = blockIdx.x * GBN;
    int b  = m0 >> 13;
    int w  = tid >> 5;
    int wm = w & 3, wn = w >> 2;          // 4 x 2 warps, warp tile 32 x 64

    // load indices (each thread: 2 chunks of 16B per tile per stage)
    int at0 = tid*2;                       // A: row = t>>2, cc = t&3
    int bt0 = tid*2;                       // B: row = t>>4, cc = t&15

    wmma::fragment<wmma::accumulator,16,16,16,float> c[2][4];
#pragma unroll
    for (int i = 0; i < 2; i++)
#pragma unroll
        for (int j = 0; j < 4; j++) wmma::fill_fragment(c[i][j], 0.f);

    // prologue: stages 0,1
#pragma unroll
    for (int s = 0; s < 2; s++) {
        int k0 = s * GBK;
#pragma unroll
        for (int j = 0; j < 2; j++) {
            int t = at0 + j;
            int row = t >> 2, cc = t & 3;
            cp16(&Asm[s*A_STAGE + row*LDA + cc*8],
                 g_in_bf + (size_t)(m0+row)*IND + k0 + cc*8);
        }
#pragma unroll
        for (int j = 0; j < 2; j++) {
            int t = bt0 + j;
            int row = t >> 4, cc = t & 15;
            cp16(&Bsm[s*B_STAGE + row*LDB + cc*8],
                 g_W_bf + (size_t)(k0+row)*HID + n0 + cc*8);
        }
        asm volatile("cp.async.commit_group;\n");
    }

    const int NKT = IND / GBK;   // 32
    for (int kt = 0; kt < NKT; kt++) {
        if (kt < NKT-2) asm volatile("cp.async.wait_group 1;\n");
        else            asm volatile("cp.async.wait_group 0;\n");
        __syncthreads();

        if (kt + 2 < NKT) {
            int s = (kt + 2) % GSTAGES;
            int k0 = (kt + 2) * GBK;
#pragma unroll
            for (int j = 0; j < 2; j++) {
                int t = at0 + j;
                int row = t >> 2, cc = t & 3;
                cp16(&Asm[s*A_STAGE + row*LDA + cc*8],
                     g_in_bf + (size_t)(m0+row)*IND + k0 + cc*8);
            }
#pragma unroll
            for (int j = 0; j < 2; j++) {
                int t = bt0 + j;
                int row = t >> 4, cc = t & 15;
                cp16(&Bsm[s*B_STAGE + row*LDB + cc*8],
                     g_W_bf + (size_t)(k0+row)*HID + n0 + cc*8);
            }
            asm volatile("cp.async.commit_group;\n");
        }

        const __nv_bfloat16* As = Asm + (kt % GSTAGES)*A_STAGE;
        const __nv_bfloat16* Bs = Bsm + (kt % GSTAGES)*B_STAGE;
#pragma unroll
        for (int kk = 0; kk < GBK; kk += 16) {
            wmma::fragment<wmma::matrix_a,16,16,16,__nv_bfloat16,wmma::row_major> a0, a1;
            wmma::load_matrix_sync(a0, As + (wm*32   )*LDA + kk, LDA);
            wmma::load_matrix_sync(a1, As + (wm*32+16)*LDA + kk, LDA);
#pragma unroll
            for (int j = 0; j < 4; j++) {
                wmma::fragment<wmma::matrix_b,16,16,16,__nv_bfloat16,wmma::row_major> bf;
                wmma::load_matrix_sync(bf, Bs + kk*LDB + wn*64 + j*16, LDB);
                wmma::mma_sync(c[0][j], a0, bf, c[0][j]);
                wmma::mma_sync(c[1][j], a1, bf, c[1][j]);
            }
        }
        __syncthreads();
    }

    // epilogue: stage C through smem, apply relu(x - Q), stream out
#pragma unroll
    for (int i = 0; i < 2; i++)
#pragma unroll
        for (int j = 0; j < 4; j++)
            wmma::store_matrix_sync(&Cs[(wm*32+i*16)*LDC + wn*64 + j*16],
                                    c[i][j], LDC, wmma::mem_row_major);
    __syncthreads();

    int c4 = tid & 31;           // float4 column group
    int r0 = tid >> 5;           // 0..7
    int col = n0 + c4*4;
    float4 q;
    {
        const float* Qb = g_Q + b*HID;
        q.x = bfeat[col+0] - Qb[col+0];
        q.y = bfeat[col+1] - Qb[col+1];
        q.z = bfeat[col+2] - Qb[col+2];
        q.w = bfeat[col+3] - Qb[col+3];
    }
#pragma unroll
    for (int t = 0; t < 16; t++) {
        int r = r0 + t*8;
        float4 v = *(float4*)&Cs[r*LDC + c4*4];
        v.x = fmaxf(v.x + q.x, 0.f);
        v.y = fmaxf(v.y + q.y, 0.f);
        v.z = fmaxf(v.z + q.z, 0.f);
        v.w = fmaxf(v.w + q.w, 0.f);
        *(float4*)(g_x + (size_t)(m0+r)*HID + col) = v;
    }
}

// ---------------- cls row ---------------------------------------------------
__global__ void k_cls(const float* __restrict__ cls) {
    g_x2[(size_t)blockIdx.x*NP*HID + threadIdx.x] = cls[threadIdx.x];
}

// ---------------- depthwise 3x3 conv, smem row-strip tiling -----------------
// block: one output image row (91 positions) x 64 channels, 256 threads
#define CONV_SMEM (3*91*64*4)   // 69888 bytes
__global__ void k_conv(const float* __restrict__ cw, const float* __restrict__ cb) {
    extern __shared__ float s[];   // [3][91][64]
    int tid = threadIdx.x;
    int cg = blockIdx.x * 64, y = blockIdx.y, b = blockIdx.z;
    int ch = tid & 63, px = tid >> 6;

#pragma unroll
    for (int dy = 0; dy < 3; dy++) {
        int yy = y + dy - 1;
        if (yy < 0 || yy >= HH) continue;
        float* srow = s + dy*91*64;
        for (int t = tid; t < 91*16; t += 256) {
            int xx = t >> 4, cc4 = t & 15;
            int gr = yy*HH + xx; if (gr >= NN) gr -= NN;   // wrap padding rows
            *(float4*)&srow[xx*64 + cc4*4] =
                *(const float4*)(g_x + ((size_t)(b*NN + gr))*HID + cg + cc4*4);
        }
    }
    __syncthreads();

    float w9[9];
#pragma unroll
    for (int k = 0; k < 9; k++) w9[k] = cw[(cg+ch)*9 + k];
    float bias = cb[cg+ch];

    for (int xx = px; xx < HH; xx += 4) {
        float acc = 0.f;
#pragma unroll
        for (int dy = 0; dy < 3; dy++) {
            int yy = y + dy - 1; if (yy < 0 || yy >= HH) continue;
#pragma unroll
            for (int dx = 0; dx < 3; dx++) {
                int x2 = xx + dx - 1; if (x2 < 0 || x2 >= HH) continue;
                acc += s[(dy*91 + x2)*64 + ch] * w9[dy*3+dx];
            }
        }
        float center = s[(91 + xx)*64 + ch];
        g_x2[((size_t)b*NP + 1 + y*HH + xx)*HID + cg + ch] = acc + bias + center;
    }
}

// ---------------- q projection + per-head key vectors u ---------------------
__global__ void k_attnprep(const float* __restrict__ Wq, const float* __restrict__ bq,
                           const float* __restrict__ Wk, const float* __restrict__ bk) {
    __shared__ float qs[HID];
    int b = blockIdx.x, tid = threadIdx.x;  // 512
    qs[tid] = g_Q[b*HID + tid];
    __syncthreads();
    float acc = bq[tid];
    for (int c = 0; c < HID; c++) acc += qs[c]*Wq[(size_t)c*HID + tid];
    __syncthreads();
    qs[tid] = acc;
    g_qvec[b*HID + tid] = acc;
    __syncthreads();
#pragma unroll
    for (int h = 0; h < NHEAD; h++) {
        float u = 0.f;
        const float* wr = Wk + (size_t)tid*HID + h*64;
        const float* qh = qs + h*64;
        for (int d = 0; d < 64; d++) u += wr[d]*qh[d];
        g_u[(b*NHEAD + h)*HID + tid] = u;
    }
    if (tid < NHEAD) {
        float qb = 0.f;
        for (int d = 0; d < 64; d++) qb += bk[tid*64 + d]*qs[tid*64 + d];
        g_qbk[b*NHEAD + tid] = qb;
    }
    for (int t = tid; t < NHEAD*HID; t += 512) g_w[b*NHEAD*HID + t] = 0.f;
}

// ---------------- logits over 8282 keys (8 heads per row pass) --------------
__global__ void k_logits() {
    __shared__ float us[NHEAD*HID];
    __shared__ float qb[NHEAD];
    int tid = threadIdx.x;  // 256
    int b = blockIdx.y;
    for (int i = tid; i < NHEAD*HID; i += 256) us[i] = g_u[b*NHEAD*HID + i];
    if (tid < NHEAD) qb[tid] = g_qbk[b*NHEAD + tid];
    __syncthreads();
    int warp = tid >> 5, lane = tid & 31;
    const float RS = 0.0441941738241592f;   // 1/sqrt(512)
    for (int it = 0; it < 4; it++) {
        int n = blockIdx.x*32 + warp*4 + it;
        if (n >= NP) break;
        const float4* row = (const float4*)(g_x2 + ((size_t)b*NP + n)*HID);
        float acc[NHEAD] = {0,0,0,0,0,0,0,0};
#pragma unroll
        for (int t = 0; t < 4; t++) {
            float4 f = row[lane + t*32];
            int c = (lane + t*32)*4;
#pragma unroll
            for (int h = 0; h < NHEAD; h++) {
                const float* uh = us + h*HID + c;
                acc[h] += f.x*uh[0] + f.y*uh[1] + f.z*uh[2] + f.w*uh[3];
            }
        }
#pragma unroll
        for (int h = 0; h < NHEAD; h++)
            for (int o = 16; o; o >>= 1) acc[h] += __shfl_xor_sync(0xffffffffu, acc[h], o);
        if (lane == 0) {
#pragma unroll
            for (int h = 0; h < NHEAD; h++)
                g_logits[((size_t)(b*NHEAD + h))*NP + n] = (acc[h] + qb[h]) * RS;
        }
    }
}

// ---------------- softmax stats (max, sumexp) per (b,h) ---------------------
__global__ void k_softmax() {
    __shared__ float red[256];
    int bh = blockIdx.x, tid = threadIdx.x;
    const float* l = g_logits + (size_t)bh*NP;
    float m = -3.4e38f;
    for (int i = tid; i < NP; i += 256) m = fmaxf(m, l[i]);
    red[tid] = m; __syncthreads();
    for (int s = 128; s; s >>= 1) { if (tid < s) red[tid] = fmaxf(red[tid], red[tid+s]); __syncthreads(); }
    m = red[0]; __syncthreads();
    float sum = 0.f;
    for (int i = tid; i < NP; i += 256) sum += expf(l[i] - m);
    red[tid] = sum; __syncthreads();
    for (int s = 128; s; s >>= 1) { if (tid < s) red[tid] += red[tid+s]; __syncthreads(); }
    if (tid == 0) { g_mx[bh] = m; g_sm[bh] = red[0]; }
}

// ---------------- weighted sums w[b,h,:] = sum_n A x2[n,:] ------------------
#define WCH 130
__global__ void k_wsum() {
    __shared__ float as[NHEAD*WCH];
    int tid = threadIdx.x;   // 512 = channel
    int b = blockIdx.y;
    int base = blockIdx.x * WCH;
    for (int idx = tid; idx < NHEAD*WCH; idx += 512) {
        int h = idx / WCH, i = idx - h*WCH;
        int n = base + i;
        float a = 0.f;
        if (n < NP) {
            int bh = b*NHEAD + h;
            a = expf(g_logits[(size_t)bh*NP + n] - g_mx[bh]) / g_sm[bh];
        }
        as[idx] = a;
    }
    __syncthreads();
    float w[NHEAD] = {0,0,0,0,0,0,0,0};
    for (int i = 0; i < WCH; i++) {
        int n = base + i;
        if (n >= NP) break;
        float v = g_x2[((size_t)b*NP + n)*HID + tid];
#pragma unroll
        for (int h = 0; h < NHEAD; h++) w[h] += as[h*WCH + i]*v;
    }
#pragma unroll
    for (int h = 0; h < NHEAD; h++)
        atomicAdd(&g_w[(b*NHEAD + h)*HID + tid], w[h]);
}

// ---------------- finale: O = q + w@Wv + bv; O += relu(O@Wo+bo); out=O@Wc+bc
__global__ void k_finale(const float* __restrict__ Wv, const float* __restrict__ bv,
                         const float* __restrict__ Wo, const float* __restrict__ bo,
                         const float* __restrict__ Wc, const float* __restrict__ bc,
                         float* __restrict__ out) {
    __shared__ float ws[NHEAD*HID];
    __shared__ float Ov[HID];
    __shared__ float red[HID];
    int b = blockIdx.x, tid = threadIdx.x;  // 512
    for (int i = tid; i < NHEAD*HID; i += 512) ws[i] = g_w[b*NHEAD*HID + i];
    __syncthreads();
    int h = tid >> 6;
    float acc = bv[tid] + g_qvec[b*HID + tid];
    const float* wh = ws + h*HID;
    for (int c = 0; c < HID; c++) acc += wh[c]*Wv[(size_t)c*HID + tid];
    Ov[tid] = acc;
    __syncthreads();
    float t2 = bo[tid];
    for (int c = 0; c < HID; c++) t2 += Ov[c]*Wo[(size_t)c*HID + tid];
    __syncthreads();
    Ov[tid] = Ov[tid] + fmaxf(t2, 0.f);
    __syncthreads();
    for (int j = 0; j < NCLS; j++) {
        red[tid] = Ov[tid]*Wc[tid*NCLS + j];
        __syncthreads();
        for (int s = 256; s; s >>= 1) { if (tid < s) red[tid] += red[tid+s]; __syncthreads(); }
        if (tid == 0) out[b*NCLS + j] = red[0] + bc[j];
        __syncthreads();
    }
}

// ---------------------------------------------------------------------------
extern "C" void kernel_launch(void* const* d_in, const int* in_sizes, int n_in,
                              void* d_out, int out_size) {
    const float* inputs  = (const float*)d_in[0];
    const float* W_feat  = (const float*)d_in[1];
    const float* b_feat  = (const float*)d_in[2];
    const float* w_enc   = (const float*)d_in[3];
    // d_in[4] = b_enc: uniform shift before sigmoid -> does not affect top-k
    const float* cls_tok = (const float*)d_in[5];
    const float* conv_w  = (const float*)d_in[6];
    const float* conv_b  = (const float*)d_in[7];
    const float* Wq = (const float*)d_in[8];
    const float* bq = (const float*)d_in[9];
    const float* Wk = (const float*)d_in[10];
    const float* bk = (const float*)d_in[11];
    const float* Wv = (const float*)d_in[12];
    const float* bv = (const float*)d_in[13];
    const float* Wo = (const float*)d_in[14];
    const float* bo = (const float*)d_in[15];
    const float* Wc = (const float*)d_in[16];
    const float* bc = (const float*)d_in[17];
    float* out = (float*)d_out;

    cudaFuncSetAttribute(k_gemm, cudaFuncAttributeMaxDynamicSharedMemorySize, GEMM_SMEM);
    cudaFuncSetAttribute(k_conv, cudaFuncAttributeMaxDynamicSharedMemorySize, CONV_SMEM);

    k_venc  <<<128, 256>>>(W_feat, w_enc);
    k_wbf   <<<IND*HID/4/256, 256>>>(W_feat);
    k_scores<<<MM/8, 256>>>(inputs);
    k_topk  <<<BB, 1024>>>();
    k_suminp<<<BB, 1024>>>(inputs);
    k_Q     <<<BB, 512>>>(W_feat, b_feat);
    k_gemm  <<<dim3(HID/GBN, MM/GBM), 256, GEMM_SMEM>>>(b_feat);
    k_cls   <<<BB, 512>>>(cls_tok);
    k_conv  <<<dim3(HID/64, HH, BB), 256, CONV_SMEM>>>(conv_w, conv_b);
    k_attnprep<<<BB, 512>>>(Wq, bq, Wk, bk);
    k_logits<<<dim3((NP+31)/32, BB), 256>>>();
    k_softmax<<<BB*NHEAD, 256>>>();
    k_wsum  <<<dim3((NP+WCH-1)/WCH, BB), 512>>>();
    k_finale<<<BB, 512>>>(Wv, bv, Wo, bo, Wc, bc, out);
}

// round 5
// speedup vs baseline: 1.2475x; 1.2475x over previous
#include <cuda_runtime.h>
#include <cuda_bf16.h>
#include <mma.h>
#include <cfloat>

using namespace nvcuda;

#define BB 4
#define NN 8192
#define IND 1024
#define HID 512
#define NHEAD 8
#define TOPK 16
#define NCLS 2
#define HH 91
#define PP (HH*HH)      // 8281
#define NP (PP+1)       // 8282 attention rows (cls + conv out)
#define MM (BB*NN)      // 32768

// ---------------- scratch (static __device__, no allocation) ----------------
__device__ __nv_bfloat16 g_in_bf[(size_t)MM*IND];   // 64 MB
__device__ __nv_bfloat16 g_W_bf[IND*HID];           // 1 MB
__device__ float g_venc[IND];
__device__ float g_scores[MM];
__device__ int   g_topk[BB*TOPK];
__device__ float g_suminp[BB*IND];
__device__ float g_Q[BB*HID];
__device__ float g_x[(size_t)MM*HID];               // relu(x - Q), 64 MB
__device__ float g_x2[(size_t)BB*NP*HID];           // cls + conv-out, 66 MB
__device__ float g_qvec[BB*HID];
__device__ float g_u[BB*NHEAD*HID];
__device__ float g_qbk[BB*NHEAD];
__device__ float g_logits[BB*NHEAD*NP];
__device__ float g_mx[BB*NHEAD];
__device__ float g_sm[BB*NHEAD];
__device__ float g_w[BB*NHEAD*HID];

// ---------------- v_enc = W_feat @ w_enc (fp32, exact scores path) ----------
__global__ void k_venc(const float* __restrict__ Wf, const float* __restrict__ wenc) {
    __shared__ float we[HID];
    int tid = threadIdx.x;
    for (int i = tid; i < HID; i += 256) we[i] = wenc[i];
    __syncthreads();
    int warp = tid >> 5, lane = tid & 31;
    int row = blockIdx.x * 8 + warp;
    const float4* r4 = (const float4*)(Wf + (size_t)row*HID);
    float acc = 0.f;
#pragma unroll
    for (int t = 0; t < 4; t++) {
        float4 f = r4[lane + t*32];
        int c = (lane + t*32)*4;
        acc += f.x*we[c] + f.y*we[c+1] + f.z*we[c+2] + f.w*we[c+3];
    }
    for (int o = 16; o; o >>= 1) acc += __shfl_xor_sync(0xffffffffu, acc, o);
    if (lane == 0) g_venc[row] = acc;
}

// ---------------- W_feat -> bf16 --------------------------------------------
__global__ void k_wbf(const float* __restrict__ Wf) {
    int i = blockIdx.x*blockDim.x + threadIdx.x;   // float4 index
    float4 f = ((const float4*)Wf)[i];
    __nv_bfloat162 lo = __floats2bfloat162_rn(f.x, f.y);
    __nv_bfloat162 hi = __floats2bfloat162_rn(f.z, f.w);
    uint2 u;
    u.x = *reinterpret_cast<unsigned*>(&lo);
    u.y = *reinterpret_cast<unsigned*>(&hi);
    ((uint2*)g_W_bf)[i] = u;
}

// ---------------- scores (fp32 GEMV) + inputs -> bf16, one pass -------------
__global__ void k_scores(const float* __restrict__ inp) {
    __shared__ float ve[IND];
    int tid = threadIdx.x;
    for (int i = tid; i < IND; i += 256) ve[i] = g_venc[i];
    __syncthreads();
    int warp = tid >> 5, lane = tid & 31;
    int row = blockIdx.x * 8 + warp;
    const float4* r4 = (const float4*)(inp + (size_t)row*IND);
    uint2* dst = (uint2*)(g_in_bf + (size_t)row*IND);
    float acc = 0.f;
#pragma unroll
    for (int t = 0; t < 8; t++) {
        int i = lane + t*32;
        float4 f = r4[i];
        int c = i*4;
        acc += f.x*ve[c] + f.y*ve[c+1] + f.z*ve[c+2] + f.w*ve[c+3];
        __nv_bfloat162 lo = __floats2bfloat162_rn(f.x, f.y);
        __nv_bfloat162 hi = __floats2bfloat162_rn(f.z, f.w);
        uint2 u;
        u.x = *reinterpret_cast<unsigned*>(&lo);
        u.y = *reinterpret_cast<unsigned*>(&hi);
        dst[i] = u;
    }
    for (int o = 16; o; o >>= 1) acc += __shfl_xor_sync(0xffffffffu, acc, o);
    if (lane == 0) g_scores[row] = acc;
}

// ---------------- top-16 per batch (warp-shuffle argmax iterations) ---------
__global__ void k_topk() {
    __shared__ float sv[NN];
    __shared__ float wv[32];
    __shared__ int   wi[32];
    int b = blockIdx.x, tid = threadIdx.x;
    int lane = tid & 31, warp = tid >> 5;
    for (int i = tid; i < NN; i += 1024) sv[i] = g_scores[b*NN + i];
    __syncthreads();
    for (int k = 0; k < TOPK; k++) {
        float bv = -FLT_MAX; int bi = 0x7fffffff;
#pragma unroll
        for (int t = 0; t < 8; t++) {
            int i = tid + t*1024;
            float v = sv[i];
            if (v > bv || (v == bv && i < bi)) { bv = v; bi = i; }
        }
#pragma unroll
        for (int o = 16; o; o >>= 1) {
            float ov = __shfl_xor_sync(0xffffffffu, bv, o);
            int   oi = __shfl_xor_sync(0xffffffffu, bi, o);
            if (ov > bv || (ov == bv && oi < bi)) { bv = ov; bi = oi; }
        }
        if (lane == 0) { wv[warp] = bv; wi[warp] = bi; }
        __syncthreads();
        if (warp == 0) {
            float v2 = wv[lane]; int i2 = wi[lane];
#pragma unroll
            for (int o = 16; o; o >>= 1) {
                float ov = __shfl_xor_sync(0xffffffffu, v2, o);
                int   oi = __shfl_xor_sync(0xffffffffu, i2, o);
                if (ov > v2 || (ov == v2 && oi < i2)) { v2 = ov; i2 = oi; }
            }
            if (lane == 0) { g_topk[b*TOPK + k] = i2; sv[i2] = -FLT_MAX; }
        }
        __syncthreads();
    }
}

// ---------------- sum of top-k input rows (fp32) ----------------------------
__global__ void k_suminp(const float* __restrict__ inp) {
    int b = blockIdx.x, tid = threadIdx.x;  // 1024 threads
    float acc = 0.f;
#pragma unroll
    for (int k = 0; k < TOPK; k++) {
        int r = g_topk[b*TOPK + k];
        acc += inp[((size_t)b*NN + r)*IND + tid];
    }
    g_suminp[b*IND + tid] = acc;
}

// ---------------- Q = suminp @ W_feat / 16 + b_feat (fp32 exact) ------------
__global__ void k_Q(const float* __restrict__ Wf, const float* __restrict__ bfeat) {
    __shared__ float s[IND];
    int b = blockIdx.x, tid = threadIdx.x;  // 512 threads
    for (int i = tid; i < IND; i += 512) s[i] = g_suminp[b*IND + i];
    __syncthreads();
    float acc = 0.f;
    for (int i = 0; i < IND; i++) acc += s[i]*Wf[(size_t)i*HID + tid];
    g_Q[b*HID + tid] = acc * (1.f/TOPK) + bfeat[tid];
}

// ---------------- main GEMM: 128x128x32, 3-stage reg pipeline, 1 bar/iter ---
#define GBM 128
#define GBN 128
#define GBK 32
#define LDA 40
#define LDB 136
#define LDC2 68
#define NSTG 3
#define A_ST (GBM*LDA)            // 5120 bf16
#define B_ST (GBK*LDB)            // 4352 bf16
#define GEMM_SMEM (NSTG*(A_ST+B_ST)*2)   // 56832 bytes (C stage 34816 reuses)

__global__ __launch_bounds__(256) void k_gemm(const float* __restrict__ bfeat) {
    extern __shared__ unsigned char dyn[];
    __nv_bfloat16* Asm = (__nv_bfloat16*)dyn;                // [3][128][40]
    __nv_bfloat16* Bsm = Asm + NSTG*A_ST;                    // [3][32][136]
    float* Cs = (float*)dyn;                                 // [128][68] staging

    int tid = threadIdx.x;
    int m0 = blockIdx.y * GBM;
    int n0 = blockIdx.x * GBN;
    int b  = m0 >> 13;
    int w  = tid >> 5;
    int wm = w & 3, wn = w >> 2;          // warp tile 32 x 64

    // A: 512 16B-chunks (row=t>>2, cc=t&3); B: 512 chunks (row=t>>4, cc=t&15)
    int ar[2], ac[2], br[2], bc[2];
#pragma unroll
    for (int j = 0; j < 2; j++) {
        int t = tid*2 + j;
        ar[j] = t >> 2;  ac[j] = t & 3;
        br[j] = t >> 4;  bc[j] = t & 15;
    }

    uint4 ra[2][2], rb[2][2];   // [set][chunk]

#define LDG_TILE(kt, set) do {                                                  \
        int k0_ = (kt)*GBK;                                                     \
        _Pragma("unroll")                                                       \
        for (int j = 0; j < 2; j++) {                                           \
            ra[set][j] = *(const uint4*)(g_in_bf + (size_t)(m0+ar[j])*IND + k0_ + ac[j]*8); \
            rb[set][j] = *(const uint4*)(g_W_bf + (size_t)(k0_+br[j])*HID + n0 + bc[j]*8);  \
        }                                                                       \
    } while (0)

#define STS_TILE(stg, set) do {                                                 \
        _Pragma("unroll")                                                       \
        for (int j = 0; j < 2; j++) {                                           \
            *(uint4*)&Asm[(stg)*A_ST + ar[j]*LDA + ac[j]*8] = ra[set][j];       \
            *(uint4*)&Bsm[(stg)*B_ST + br[j]*LDB + bc[j]*8] = rb[set][j];       \
        }                                                                       \
    } while (0)

    wmma::fragment<wmma::accumulator,16,16,16,float> c[2][4];
#pragma unroll
    for (int i = 0; i < 2; i++)
#pragma unroll
        for (int j = 0; j < 4; j++) wmma::fill_fragment(c[i][j], 0.f);

    // prologue: fill stages 0,1; preload tile 2 into regs
    LDG_TILE(0, 0); STS_TILE(0, 0);
    LDG_TILE(1, 1); STS_TILE(1, 1);
    LDG_TILE(2, 0);

    const int NKT = IND / GBK;   // 32
    for (int kt = 0; kt < NKT; kt++) {
        __syncthreads();
        int kf = kt + 2;
        if (kf < NKT) STS_TILE(kf % NSTG, kf & 1);
        int kl = kt + 3;
        if (kl < NKT) LDG_TILE(kl, kl & 1);

        const __nv_bfloat16* As = Asm + (kt % NSTG)*A_ST;
        const __nv_bfloat16* Bs = Bsm + (kt % NSTG)*B_ST;
#pragma unroll
        for (int kk = 0; kk < GBK; kk += 16) {
            wmma::fragment<wmma::matrix_a,16,16,16,__nv_bfloat16,wmma::row_major> a0, a1;
            wmma::load_matrix_sync(a0, As + (wm*32   )*LDA + kk, LDA);
            wmma::load_matrix_sync(a1, As + (wm*32+16)*LDA + kk, LDA);
#pragma unroll
            for (int j = 0; j < 4; j++) {
                wmma::fragment<wmma::matrix_b,16,16,16,__nv_bfloat16,wmma::row_major> bf;
                wmma::load_matrix_sync(bf, Bs + kk*LDB + wn*64 + j*16, LDB);
                wmma::mma_sync(c[0][j], a0, bf, c[0][j]);
                wmma::mma_sync(c[1][j], a1, bf, c[1][j]);
            }
        }
    }
    __syncthreads();

    // two-phase epilogue: stage 128x64 halves through smem, fuse relu(x - Q)
    const float* Qb = g_Q + b*HID;
    int c4 = tid & 15, r0 = tid >> 4;
#pragma unroll
    for (int p = 0; p < 2; p++) {
        if (wn == p) {
#pragma unroll
            for (int i = 0; i < 2; i++)
#pragma unroll
                for (int j = 0; j < 4; j++)
                    wmma::store_matrix_sync(&Cs[(wm*32+i*16)*LDC2 + j*16],
                                            c[i][j], LDC2, wmma::mem_row_major);
        }
        __syncthreads();
        int col = n0 + p*64 + c4*4;
        float4 q;
        q.x = bfeat[col+0] - Qb[col+0];
        q.y = bfeat[col+1] - Qb[col+1];
        q.z = bfeat[col+2] - Qb[col+2];
        q.w = bfeat[col+3] - Qb[col+3];
#pragma unroll
        for (int t = 0; t < 8; t++) {
            int r = r0 + t*16;
            float4 v = *(float4*)&Cs[r*LDC2 + c4*4];
            v.x = fmaxf(v.x + q.x, 0.f);
            v.y = fmaxf(v.y + q.y, 0.f);
            v.z = fmaxf(v.z + q.z, 0.f);
            v.w = fmaxf(v.w + q.w, 0.f);
            *(float4*)(g_x + (size_t)(m0+r)*HID + col) = v;
        }
        __syncthreads();
    }
#undef LDG_TILE
#undef STS_TILE
}

// ---------------- cls row ---------------------------------------------------
__global__ void k_cls(const float* __restrict__ cls) {
    g_x2[(size_t)blockIdx.x*NP*HID + threadIdx.x] = cls[threadIdx.x];
}

// ---------------- depthwise 3x3 conv (round-1 version, direct L2 reads) -----
__global__ void k_conv(const float* __restrict__ cw, const float* __restrict__ cb) {
    __shared__ float cws[HID*9];
    __shared__ float cbs[HID];
    int tid = threadIdx.x;   // 512 = channel
    int b = blockIdx.y;
#pragma unroll
    for (int k = 0; k < 9; k++) cws[tid*9 + k] = cw[tid*9 + k];
    cbs[tid] = cb[tid];
    __syncthreads();
    int p0 = blockIdx.x * 16;
    for (int i = 0; i < 16; i++) {
        int p = p0 + i;
        if (p >= PP) break;
        int y = p / HH, x = p - y*HH;
        float acc = 0.f, center = 0.f;
#pragma unroll
        for (int dy = -1; dy <= 1; dy++) {
            int yy = y + dy; if (yy < 0 || yy >= HH) continue;
#pragma unroll
            for (int dx = -1; dx <= 1; dx++) {
                int xx = x + dx; if (xx < 0 || xx >= HH) continue;
                int pp2 = yy*HH + xx;
                int r = (pp2 < NN) ? pp2 : pp2 - NN;   // wrap padding rows
                float v = g_x[((size_t)(b*NN + r))*HID + tid];
                acc += v * cws[tid*9 + (dy+1)*3 + (dx+1)];
                if (dy == 0 && dx == 0) center = v;
            }
        }
        g_x2[((size_t)b*NP + 1 + p)*HID + tid] = acc + cbs[tid] + center;
    }
}

// ---------------- q projection + per-head key vectors u ---------------------
__global__ void k_attnprep(const float* __restrict__ Wq, const float* __restrict__ bq,
                           const float* __restrict__ Wk, const float* __restrict__ bk) {
    __shared__ float qs[HID];
    int b = blockIdx.x, tid = threadIdx.x;  // 512
    qs[tid] = g_Q[b*HID + tid];
    __syncthreads();
    float acc = bq[tid];
    for (int c = 0; c < HID; c++) acc += qs[c]*Wq[(size_t)c*HID + tid];
    __syncthreads();
    qs[tid] = acc;
    g_qvec[b*HID + tid] = acc;
    __syncthreads();
#pragma unroll
    for (int h = 0; h < NHEAD; h++) {
        float u = 0.f;
        const float* wr = Wk + (size_t)tid*HID + h*64;
        const float* qh = qs + h*64;
        for (int d = 0; d < 64; d++) u += wr[d]*qh[d];
        g_u[(b*NHEAD + h)*HID + tid] = u;
    }
    if (tid < NHEAD) {
        float qb = 0.f;
        for (int d = 0; d < 64; d++) qb += bk[tid*64 + d]*qs[tid*64 + d];
        g_qbk[b*NHEAD + tid] = qb;
    }
    for (int t = tid; t < NHEAD*HID; t += 512) g_w[b*NHEAD*HID + t] = 0.f;
}

// ---------------- logits over 8282 keys (8 heads per row pass) --------------
__global__ void k_logits() {
    __shared__ float us[NHEAD*HID];
    __shared__ float qb[NHEAD];
    int tid = threadIdx.x;  // 256
    int b = blockIdx.y;
    for (int i = tid; i < NHEAD*HID; i += 256) us[i] = g_u[b*NHEAD*HID + i];
    if (tid < NHEAD) qb[tid] = g_qbk[b*NHEAD + tid];
    __syncthreads();
    int warp = tid >> 5, lane = tid & 31;
    const float RS = 0.0441941738241592f;   // 1/sqrt(512)
    for (int it = 0; it < 4; it++) {
        int n = blockIdx.x*32 + warp*4 + it;
        if (n >= NP) break;
        const float4* row = (const float4*)(g_x2 + ((size_t)b*NP + n)*HID);
        float acc[NHEAD] = {0,0,0,0,0,0,0,0};
#pragma unroll
        for (int t = 0; t < 4; t++) {
            float4 f = row[lane + t*32];
            int c = (lane + t*32)*4;
#pragma unroll
            for (int h = 0; h < NHEAD; h++) {
                const float* uh = us + h*HID + c;
                acc[h] += f.x*uh[0] + f.y*uh[1] + f.z*uh[2] + f.w*uh[3];
            }
        }
#pragma unroll
        for (int h = 0; h < NHEAD; h++)
            for (int o = 16; o; o >>= 1) acc[h] += __shfl_xor_sync(0xffffffffu, acc[h], o);
        if (lane == 0) {
#pragma unroll
            for (int h = 0; h < NHEAD; h++)
                g_logits[((size_t)(b*NHEAD + h))*NP + n] = (acc[h] + qb[h]) * RS;
        }
    }
}

// ---------------- softmax stats (max, sumexp) per (b,h) ---------------------
__global__ void k_softmax() {
    __shared__ float red[256];
    int bh = blockIdx.x, tid = threadIdx.x;
    const float* l = g_logits + (size_t)bh*NP;
    float m = -3.4e38f;
    for (int i = tid; i < NP; i += 256) m = fmaxf(m, l[i]);
    red[tid] = m; __syncthreads();
    for (int s = 128; s; s >>= 1) { if (tid < s) red[tid] = fmaxf(red[tid], red[tid+s]); __syncthreads(); }
    m = red[0]; __syncthreads();
    float sum = 0.f;
    for (int i = tid; i < NP; i += 256) sum += expf(l[i] - m);
    red[tid] = sum; __syncthreads();
    for (int s = 128; s; s >>= 1) { if (tid < s) red[tid] += red[tid+s]; __syncthreads(); }
    if (tid == 0) { g_mx[bh] = m; g_sm[bh] = red[0]; }
}

// ---------------- weighted sums w[b,h,:] = sum_n A x2[n,:] ------------------
#define WCH 130
__global__ void k_wsum() {
    __shared__ float as[NHEAD*WCH];
    int tid = threadIdx.x;   // 512 = channel
    int b = blockIdx.y;
    int base = blockIdx.x * WCH;
    for (int idx = tid; idx < NHEAD*WCH; idx += 512) {
        int h = idx / WCH, i = idx - h*WCH;
        int n = base + i;
        float a = 0.f;
        if (n < NP) {
            int bh = b*NHEAD + h;
            a = expf(g_logits[(size_t)bh*NP + n] - g_mx[bh]) / g_sm[bh];
        }
        as[idx] = a;
    }
    __syncthreads();
    float w[NHEAD] = {0,0,0,0,0,0,0,0};
    for (int i = 0; i < WCH; i++) {
        int n = base + i;
        if (n >= NP) break;
        float v = g_x2[((size_t)b*NP + n)*HID + tid];
#pragma unroll
        for (int h = 0; h < NHEAD; h++) w[h] += as[h*WCH + i]*v;
    }
#pragma unroll
    for (int h = 0; h < NHEAD; h++)
        atomicAdd(&g_w[(b*NHEAD + h)*HID + tid], w[h]);
}

// ---------------- finale: O = q + w@Wv + bv; O += relu(O@Wo+bo); out=O@Wc+bc
__global__ void k_finale(const float* __restrict__ Wv, const float* __restrict__ bv,
                         const float* __restrict__ Wo, const float* __restrict__ bo,
                         const float* __restrict__ Wc, const float* __restrict__ bc,
                         float* __restrict__ out) {
    __shared__ float ws[NHEAD*HID];
    __shared__ float Ov[HID];
    __shared__ float red[HID];
    int b = blockIdx.x, tid = threadIdx.x;  // 512
    for (int i = tid; i < NHEAD*HID; i += 512) ws[i] = g_w[b*NHEAD*HID + i];
    __syncthreads();
    int h = tid >> 6;
    float acc = bv[tid] + g_qvec[b*HID + tid];
    const float* wh = ws + h*HID;
    for (int c = 0; c < HID; c++) acc += wh[c]*Wv[(size_t)c*HID + tid];
    Ov[tid] = acc;
    __syncthreads();
    float t2 = bo[tid];
    for (int c = 0; c < HID; c++) t2 += Ov[c]*Wo[(size_t)c*HID + tid];
    __syncthreads();
    Ov[tid] = Ov[tid] + fmaxf(t2, 0.f);
    __syncthreads();
    for (int j = 0; j < NCLS; j++) {
        red[tid] = Ov[tid]*Wc[tid*NCLS + j];
        __syncthreads();
        for (int s = 256; s; s >>= 1) { if (tid < s) red[tid] += red[tid+s]; __syncthreads(); }
        if (tid == 0) out[b*NCLS + j] = red[0] + bc[j];
        __syncthreads();
    }
}

// ---------------------------------------------------------------------------
extern "C" void kernel_launch(void* const* d_in, const int* in_sizes, int n_in,
                              void* d_out, int out_size) {
    const float* inputs  = (const float*)d_in[0];
    const float* W_feat  = (const float*)d_in[1];
    const float* b_feat  = (const float*)d_in[2];
    const float* w_enc   = (const float*)d_in[3];
    // d_in[4] = b_enc: uniform shift before sigmoid -> does not affect top-k
    const float* cls_tok = (const float*)d_in[5];
    const float* conv_w  = (const float*)d_in[6];
    const float* conv_b  = (const float*)d_in[7];
    const float* Wq = (const float*)d_in[8];
    const float* bq = (const float*)d_in[9];
    const float* Wk = (const float*)d_in[10];
    const float* bk = (const float*)d_in[11];
    const float* Wv = (const float*)d_in[12];
    const float* bv = (const float*)d_in[13];
    const float* Wo = (const float*)d_in[14];
    const float* bo = (const float*)d_in[15];
    const float* Wc = (const float*)d_in[16];
    const float* bc = (const float*)d_in[17];
    float* out = (float*)d_out;

    cudaFuncSetAttribute(k_gemm, cudaFuncAttributeMaxDynamicSharedMemorySize, GEMM_SMEM);

    k_venc  <<<128, 256>>>(W_feat, w_enc);
    k_wbf   <<<IND*HID/4/256, 256>>>(W_feat);
    k_scores<<<MM/8, 256>>>(inputs);
    k_topk  <<<BB, 1024>>>();
    k_suminp<<<BB, 1024>>>(inputs);
    k_Q     <<<BB, 512>>>(W_feat, b_feat);
    k_gemm  <<<dim3(HID/GBN, MM/GBM), 256, GEMM_SMEM>>>(b_feat);
    k_cls   <<<BB, 512>>>(cls_tok);
    k_conv  <<<dim3((PP+15)/16, BB), 512>>>(conv_w, conv_b);
    k_attnprep<<<BB, 512>>>(Wq, bq, Wk, bk);
    k_logits<<<dim3((NP+31)/32, BB), 256>>>();
    k_softmax<<<BB*NHEAD, 256>>>();
    k_wsum  <<<dim3((NP+WCH-1)/WCH, BB), 512>>>();
    k_finale<<<BB, 512>>>(Wv, bv, Wo, bo, Wc, bc, out);
}

// round 6
// speedup vs baseline: 1.3953x; 1.1185x over previous
#include <cuda_runtime.h>
#include <cuda_bf16.h>
#include <mma.h>
#include <cfloat>

using namespace nvcuda;

#define BB 4
#define NN 8192
#define IND 1024
#define HID 512
#define NHEAD 8
#define TOPK 16
#define NCLS 2
#define HH 91
#define PP (HH*HH)      // 8281
#define NP (PP+1)       // 8282 attention rows (cls + conv out)
#define MM (BB*NN)      // 32768

// ---------------- scratch (static __device__, no allocation) ----------------
__device__ __nv_bfloat16 g_in_bf[(size_t)MM*IND];   // 64 MB
__device__ __nv_bfloat16 g_W_bf[IND*HID];           // 1 MB
__device__ float g_venc[IND];
__device__ float g_scores[MM];
__device__ int   g_topk[BB*TOPK];
__device__ float g_Q[BB*HID];
__device__ float g_x[(size_t)MM*HID];               // relu(x - Q), 64 MB
__device__ __nv_bfloat16 g_x2[(size_t)BB*NP*HID];   // cls + conv-out, 33 MB (bf16)
__device__ float g_qvec[BB*HID];
__device__ float g_u[BB*NHEAD*HID];
__device__ float g_qbk[BB*NHEAD];
__device__ float g_logits[BB*NHEAD*NP];
__device__ float g_mx[BB*NHEAD];
__device__ float g_sm[BB*NHEAD];
__device__ float g_w[BB*NHEAD*HID];

// ---------------- fused: v_enc = W_feat @ w_enc  +  W_feat -> bf16 ----------
__global__ void k_venc_wbf(const float* __restrict__ Wf, const float* __restrict__ wenc) {
    int tid = threadIdx.x;
    if (blockIdx.x < 128) {
        __shared__ float we[HID];
        for (int i = tid; i < HID; i += 256) we[i] = wenc[i];
        __syncthreads();
        int warp = tid >> 5, lane = tid & 31;
        int row = blockIdx.x * 8 + warp;
        const float4* r4 = (const float4*)(Wf + (size_t)row*HID);
        float acc = 0.f;
#pragma unroll
        for (int t = 0; t < 4; t++) {
            float4 f = r4[lane + t*32];
            int c = (lane + t*32)*4;
            acc += f.x*we[c] + f.y*we[c+1] + f.z*we[c+2] + f.w*we[c+3];
        }
        for (int o = 16; o; o >>= 1) acc += __shfl_xor_sync(0xffffffffu, acc, o);
        if (lane == 0) g_venc[row] = acc;
    } else {
        int i = (blockIdx.x - 128)*256 + tid;      // float4 index
        float4 f = ((const float4*)Wf)[i];
        __nv_bfloat162 lo = __floats2bfloat162_rn(f.x, f.y);
        __nv_bfloat162 hi = __floats2bfloat162_rn(f.z, f.w);
        uint2 u;
        u.x = *reinterpret_cast<unsigned*>(&lo);
        u.y = *reinterpret_cast<unsigned*>(&hi);
        ((uint2*)g_W_bf)[i] = u;
    }
}

// ---------------- scores (fp32 GEMV) + inputs -> bf16, one pass -------------
__global__ void k_scores(const float* __restrict__ inp) {
    __shared__ float ve[IND];
    int tid = threadIdx.x;
    for (int i = tid; i < IND; i += 256) ve[i] = g_venc[i];
    __syncthreads();
    int warp = tid >> 5, lane = tid & 31;
    int row = blockIdx.x * 8 + warp;
    const float4* r4 = (const float4*)(inp + (size_t)row*IND);
    uint2* dst = (uint2*)(g_in_bf + (size_t)row*IND);
    float acc = 0.f;
#pragma unroll
    for (int t = 0; t < 8; t++) {
        int i = lane + t*32;
        float4 f = r4[i];
        int c = i*4;
        acc += f.x*ve[c] + f.y*ve[c+1] + f.z*ve[c+2] + f.w*ve[c+3];
        __nv_bfloat162 lo = __floats2bfloat162_rn(f.x, f.y);
        __nv_bfloat162 hi = __floats2bfloat162_rn(f.z, f.w);
        uint2 u;
        u.x = *reinterpret_cast<unsigned*>(&lo);
        u.y = *reinterpret_cast<unsigned*>(&hi);
        dst[i] = u;
    }
    for (int o = 16; o; o >>= 1) acc += __shfl_xor_sync(0xffffffffu, acc, o);
    if (lane == 0) g_scores[row] = acc;
}

// ---------------- top-16 per batch (warp-shuffle argmax iterations) ---------
__global__ void k_topk() {
    __shared__ float sv[NN];
    __shared__ float wv[32];
    __shared__ int   wi[32];
    int b = blockIdx.x, tid = threadIdx.x;
    int lane = tid & 31, warp = tid >> 5;
    for (int i = tid; i < NN; i += 1024) sv[i] = g_scores[b*NN + i];
    __syncthreads();
    for (int k = 0; k < TOPK; k++) {
        float bv = -FLT_MAX; int bi = 0x7fffffff;
#pragma unroll
        for (int t = 0; t < 8; t++) {
            int i = tid + t*1024;
            float v = sv[i];
            if (v > bv || (v == bv && i < bi)) { bv = v; bi = i; }
        }
#pragma unroll
        for (int o = 16; o; o >>= 1) {
            float ov = __shfl_xor_sync(0xffffffffu, bv, o);
            int   oi = __shfl_xor_sync(0xffffffffu, bi, o);
            if (ov > bv || (ov == bv && oi < bi)) { bv = ov; bi = oi; }
        }
        if (lane == 0) { wv[warp] = bv; wi[warp] = bi; }
        __syncthreads();
        if (warp == 0) {
            float v2 = wv[lane]; int i2 = wi[lane];
#pragma unroll
            for (int o = 16; o; o >>= 1) {
                float ov = __shfl_xor_sync(0xffffffffu, v2, o);
                int   oi = __shfl_xor_sync(0xffffffffu, i2, o);
                if (ov > v2 || (ov == v2 && oi < i2)) { v2 = ov; i2 = oi; }
            }
            if (lane == 0) { g_topk[b*TOPK + k] = i2; sv[i2] = -FLT_MAX; }
        }
        __syncthreads();
    }
}

// ---------------- fused: suminp + Q = suminp@W_feat/16 + b_feat (fp32) ------
__global__ void k_sumQ(const float* __restrict__ inp, const float* __restrict__ Wf,
                       const float* __restrict__ bfeat) {
    __shared__ float s[IND];
    __shared__ float p2[HID];
    int b = blockIdx.x, tid = threadIdx.x;  // 1024 threads
    float acc = 0.f;
#pragma unroll
    for (int k = 0; k < TOPK; k++) {
        int r = g_topk[b*TOPK + k];
        acc += inp[((size_t)b*NN + r)*IND + tid];
    }
    s[tid] = acc;
    __syncthreads();
    int col = tid & 511, half = tid >> 9;
    float a = 0.f;
    int i0 = half*512;
    for (int i = i0; i < i0 + 512; i++) a += s[i]*Wf[(size_t)i*HID + col];
    if (half) p2[col] = a;
    __syncthreads();
    if (!half) g_Q[b*HID + col] = (a + p2[col]) * (1.f/TOPK) + bfeat[col];
}

// ---------------- main GEMM (round-1 recipe: 128x64, static smem, 6 CTA/SM) -
__global__ __launch_bounds__(256) void k_gemm(const float* __restrict__ bfeat) {
    __shared__ __align__(16) unsigned char raw[128*68*4];
    __nv_bfloat16 (*As)[72] = reinterpret_cast<__nv_bfloat16(*)[72]>(raw);
    __nv_bfloat16 (*Bs)[72] = reinterpret_cast<__nv_bfloat16(*)[72]>(raw + 128*72*2);
    float (*Es)[68] = reinterpret_cast<float(*)[68]>(raw);

    int tid = threadIdx.x;
    int m0 = blockIdx.y * 128;
    int n0 = blockIdx.x * 64;
    int b  = m0 >> 13;
    int wid = tid >> 5;
    int wm = wid >> 1, wn = wid & 1;

    int cc = tid & 63;
    float qval = bfeat[n0 + cc] - g_Q[b*HID + n0 + cc];

    wmma::fragment<wmma::accumulator,16,16,16,float> c[2][2];
#pragma unroll
    for (int i = 0; i < 2; i++)
#pragma unroll
        for (int j = 0; j < 2; j++) wmma::fill_fragment(c[i][j], 0.f);

    for (int k0 = 0; k0 < IND; k0 += 64) {
        __syncthreads();
#pragma unroll
        for (int t = 0; t < 4; t++) {           // A tile: 128 x 64
            int idx = tid + t*256;
            int row = idx >> 3, v = idx & 7;
            *(float4*)&As[row][v*8] =
                ((const float4*)(g_in_bf + (size_t)(m0+row)*IND + k0))[v];
        }
#pragma unroll
        for (int t = 0; t < 2; t++) {           // B tile: 64 x 64
            int idx = tid + t*256;
            int row = idx >> 3, v = idx & 7;
            *(float4*)&Bs[row][v*8] =
                ((const float4*)(g_W_bf + (size_t)(k0+row)*HID + n0))[v];
        }
        __syncthreads();
#pragma unroll
        for (int kk = 0; kk < 64; kk += 16) {
            wmma::fragment<wmma::matrix_a,16,16,16,__nv_bfloat16,wmma::row_major> a0, a1;
            wmma::fragment<wmma::matrix_b,16,16,16,__nv_bfloat16,wmma::row_major> b0, b1;
            wmma::load_matrix_sync(a0, &As[wm*32][kk], 72);
            wmma::load_matrix_sync(a1, &As[wm*32+16][kk], 72);
            wmma::load_matrix_sync(b0, &Bs[kk][wn*32], 72);
            wmma::load_matrix_sync(b1, &Bs[kk][wn*32+16], 72);
            wmma::mma_sync(c[0][0], a0, b0, c[0][0]);
            wmma::mma_sync(c[0][1], a0, b1, c[0][1]);
            wmma::mma_sync(c[1][0], a1, b0, c[1][0]);
            wmma::mma_sync(c[1][1], a1, b1, c[1][1]);
        }
    }
    __syncthreads();
#pragma unroll
    for (int i = 0; i < 2; i++)
#pragma unroll
        for (int j = 0; j < 2; j++)
            wmma::store_matrix_sync(&Es[wm*32+i*16][wn*32+j*16], c[i][j], 68,
                                    wmma::mem_row_major);
    __syncthreads();
    int r0 = tid >> 6;
#pragma unroll
    for (int t = 0; t < 32; t++) {
        int r = r0 + t*4;
        g_x[(size_t)(m0 + r)*HID + n0 + cc] = fmaxf(Es[r][cc] + qval, 0.f);
    }
}

// ---------------- depthwise 3x3 conv (direct L2 reads) + cls row, bf16 out --
__global__ void k_conv(const float* __restrict__ cw, const float* __restrict__ cb,
                       const float* __restrict__ cls) {
    __shared__ float cws[HID*9];
    __shared__ float cbs[HID];
    int tid = threadIdx.x;   // 512 = channel
    int b = blockIdx.y;
#pragma unroll
    for (int k = 0; k < 9; k++) cws[tid*9 + k] = cw[tid*9 + k];
    cbs[tid] = cb[tid];
    if (blockIdx.x == 0)     // cls token row
        g_x2[(size_t)b*NP*HID + tid] = __float2bfloat16(cls[tid]);
    __syncthreads();
    int p0 = blockIdx.x * 16;
    for (int i = 0; i < 16; i++) {
        int p = p0 + i;
        if (p >= PP) break;
        int y = p / HH, x = p - y*HH;
        float acc = 0.f, center = 0.f;
#pragma unroll
        for (int dy = -1; dy <= 1; dy++) {
            int yy = y + dy; if (yy < 0 || yy >= HH) continue;
#pragma unroll
            for (int dx = -1; dx <= 1; dx++) {
                int xx = x + dx; if (xx < 0 || xx >= HH) continue;
                int pp2 = yy*HH + xx;
                int r = (pp2 < NN) ? pp2 : pp2 - NN;   // wrap padding rows
                float v = g_x[((size_t)(b*NN + r))*HID + tid];
                acc += v * cws[tid*9 + (dy+1)*3 + (dx+1)];
                if (dy == 0 && dx == 0) center = v;
            }
        }
        g_x2[((size_t)b*NP + 1 + p)*HID + tid] = __float2bfloat16(acc + cbs[tid] + center);
    }
}

// ---------------- q projection + per-head key vectors u ---------------------
__global__ void k_attnprep(const float* __restrict__ Wq, const float* __restrict__ bq,
                           const float* __restrict__ Wk, const float* __restrict__ bk) {
    __shared__ float qs[HID];
    int b = blockIdx.x, tid = threadIdx.x;  // 512
    qs[tid] = g_Q[b*HID + tid];
    __syncthreads();
    float acc = bq[tid];
    for (int c = 0; c < HID; c++) acc += qs[c]*Wq[(size_t)c*HID + tid];
    __syncthreads();
    qs[tid] = acc;
    g_qvec[b*HID + tid] = acc;
    __syncthreads();
#pragma unroll
    for (int h = 0; h < NHEAD; h++) {
        float u = 0.f;
        const float* wr = Wk + (size_t)tid*HID + h*64;
        const float* qh = qs + h*64;
        for (int d = 0; d < 64; d++) u += wr[d]*qh[d];
        g_u[(b*NHEAD + h)*HID + tid] = u;
    }
    if (tid < NHEAD) {
        float qb = 0.f;
        for (int d = 0; d < 64; d++) qb += bk[tid*64 + d]*qs[tid*64 + d];
        g_qbk[b*NHEAD + tid] = qb;
    }
    for (int t = tid; t < NHEAD*HID; t += 512) g_w[b*NHEAD*HID + t] = 0.f;
}

// ---------------- logits over 8282 keys (bf16 x2, 8 heads per pass) ---------
__global__ void k_logits() {
    __shared__ float us[NHEAD*HID];
    __shared__ float qb[NHEAD];
    int tid = threadIdx.x;  // 256
    int b = blockIdx.y;
    for (int i = tid; i < NHEAD*HID; i += 256) us[i] = g_u[b*NHEAD*HID + i];
    if (tid < NHEAD) qb[tid] = g_qbk[b*NHEAD + tid];
    __syncthreads();
    int warp = tid >> 5, lane = tid & 31;
    const float RS = 0.0441941738241592f;   // 1/sqrt(512)
    for (int it = 0; it < 4; it++) {
        int n = blockIdx.x*32 + warp*4 + it;
        if (n >= NP) break;
        const uint4* row = (const uint4*)(g_x2 + ((size_t)b*NP + n)*HID);  // 64 x uint4
        float acc[NHEAD] = {0,0,0,0,0,0,0,0};
#pragma unroll
        for (int t = 0; t < 2; t++) {
            int i = lane + t*32;
            uint4 u4 = row[i];
            int c = i*8;
            float2 f0 = __bfloat1622float2(*reinterpret_cast<__nv_bfloat162*>(&u4.x));
            float2 f1 = __bfloat1622float2(*reinterpret_cast<__nv_bfloat162*>(&u4.y));
            float2 f2 = __bfloat1622float2(*reinterpret_cast<__nv_bfloat162*>(&u4.z));
            float2 f3 = __bfloat1622float2(*reinterpret_cast<__nv_bfloat162*>(&u4.w));
#pragma unroll
            for (int h = 0; h < NHEAD; h++) {
                const float* uh = us + h*HID + c;
                acc[h] += f0.x*uh[0] + f0.y*uh[1] + f1.x*uh[2] + f1.y*uh[3]
                        + f2.x*uh[4] + f2.y*uh[5] + f3.x*uh[6] + f3.y*uh[7];
            }
        }
#pragma unroll
        for (int h = 0; h < NHEAD; h++)
            for (int o = 16; o; o >>= 1) acc[h] += __shfl_xor_sync(0xffffffffu, acc[h], o);
        if (lane == 0) {
#pragma unroll
            for (int h = 0; h < NHEAD; h++)
                g_logits[((size_t)(b*NHEAD + h))*NP + n] = (acc[h] + qb[h]) * RS;
        }
    }
}

// ---------------- softmax stats (max, sumexp) per (b,h) ---------------------
__global__ void k_softmax() {
    __shared__ float red[256];
    int bh = blockIdx.x, tid = threadIdx.x;
    const float* l = g_logits + (size_t)bh*NP;
    float m = -3.4e38f;
    for (int i = tid; i < NP; i += 256) m = fmaxf(m, l[i]);
    red[tid] = m; __syncthreads();
    for (int s = 128; s; s >>= 1) { if (tid < s) red[tid] = fmaxf(red[tid], red[tid+s]); __syncthreads(); }
    m = red[0]; __syncthreads();
    float sum = 0.f;
    for (int i = tid; i < NP; i += 256) sum += expf(l[i] - m);
    red[tid] = sum; __syncthreads();
    for (int s = 128; s; s >>= 1) { if (tid < s) red[tid] += red[tid+s]; __syncthreads(); }
    if (tid == 0) { g_mx[bh] = m; g_sm[bh] = red[0]; }
}

// ---------------- weighted sums w[b,h,:] = sum_n A x2[n,:] (bf16 x2) --------
#define WCH 130
__global__ void k_wsum() {
    __shared__ float as[NHEAD*WCH];
    int tid = threadIdx.x;   // 512 = channel
    int b = blockIdx.y;
    int base = blockIdx.x * WCH;
    for (int idx = tid; idx < NHEAD*WCH; idx += 512) {
        int h = idx / WCH, i = idx - h*WCH;
        int n = base + i;
        float a = 0.f;
        if (n < NP) {
            int bh = b*NHEAD + h;
            a = expf(g_logits[(size_t)bh*NP + n] - g_mx[bh]) / g_sm[bh];
        }
        as[idx] = a;
    }
    __syncthreads();
    float w[NHEAD] = {0,0,0,0,0,0,0,0};
    for (int i = 0; i < WCH; i++) {
        int n = base + i;
        if (n >= NP) break;
        float v = __bfloat162float(g_x2[((size_t)b*NP + n)*HID + tid]);
#pragma unroll
        for (int h = 0; h < NHEAD; h++) w[h] += as[h*WCH + i]*v;
    }
#pragma unroll
    for (int h = 0; h < NHEAD; h++)
        atomicAdd(&g_w[(b*NHEAD + h)*HID + tid], w[h]);
}

// ---------------- finale: O = q + w@Wv + bv; O += relu(O@Wo+bo); out=O@Wc+bc
__global__ void k_finale(const float* __restrict__ Wv, const float* __restrict__ bv,
                         const float* __restrict__ Wo, const float* __restrict__ bo,
                         const float* __restrict__ Wc, const float* __restrict__ bc,
                         float* __restrict__ out) {
    __shared__ float ws[NHEAD*HID];
    __shared__ float Ov[HID];
    __shared__ float red[HID];
    int b = blockIdx.x, tid = threadIdx.x;  // 512
    for (int i = tid; i < NHEAD*HID; i += 512) ws[i] = g_w[b*NHEAD*HID + i];
    __syncthreads();
    int h = tid >> 6;
    float acc = bv[tid] + g_qvec[b*HID + tid];
    const float* wh = ws + h*HID;
    for (int c = 0; c < HID; c++) acc += wh[c]*Wv[(size_t)c*HID + tid];
    Ov[tid] = acc;
    __syncthreads();
    float t2 = bo[tid];
    for (int c = 0; c < HID; c++) t2 += Ov[c]*Wo[(size_t)c*HID + tid];
    __syncthreads();
    Ov[tid] = Ov[tid] + fmaxf(t2, 0.f);
    __syncthreads();
    for (int j = 0; j < NCLS; j++) {
        red[tid] = Ov[tid]*Wc[tid*NCLS + j];
        __syncthreads();
        for (int s = 256; s; s >>= 1) { if (tid < s) red[tid] += red[tid+s]; __syncthreads(); }
        if (tid == 0) out[b*NCLS + j] = red[0] + bc[j];
        __syncthreads();
    }
}

// ---------------------------------------------------------------------------
extern "C" void kernel_launch(void* const* d_in, const int* in_sizes, int n_in,
                              void* d_out, int out_size) {
    const float* inputs  = (const float*)d_in[0];
    const float* W_feat  = (const float*)d_in[1];
    const float* b_feat  = (const float*)d_in[2];
    const float* w_enc   = (const float*)d_in[3];
    // d_in[4] = b_enc: uniform shift before sigmoid -> does not affect top-k
    const float* cls_tok = (const float*)d_in[5];
    const float* conv_w  = (const float*)d_in[6];
    const float* conv_b  = (const float*)d_in[7];
    const float* Wq = (const float*)d_in[8];
    const float* bq = (const float*)d_in[9];
    const float* Wk = (const float*)d_in[10];
    const float* bk = (const float*)d_in[11];
    const float* Wv = (const float*)d_in[12];
    const float* bv = (const float*)d_in[13];
    const float* Wo = (const float*)d_in[14];
    const float* bo = (const float*)d_in[15];
    const float* Wc = (const float*)d_in[16];
    const float* bc = (const float*)d_in[17];
    float* out = (float*)d_out;

    k_venc_wbf<<<128 + IND*HID/4/256, 256>>>(W_feat, w_enc);
    k_scores<<<MM/8, 256>>>(inputs);
    k_topk  <<<BB, 1024>>>();
    k_sumQ  <<<BB, 1024>>>(inputs, W_feat, b_feat);
    k_gemm  <<<dim3(HID/64, MM/128), 256>>>(b_feat);
    k_conv  <<<dim3((PP+15)/16, BB), 512>>>(conv_w, conv_b, cls_tok);
    k_attnprep<<<BB, 512>>>(Wq, bq, Wk, bk);
    k_logits<<<dim3((NP+31)/32, BB), 256>>>();
    k_softmax<<<BB*NHEAD, 256>>>();
    k_wsum  <<<dim3((NP+WCH-1)/WCH, BB), 512>>>();
    k_finale<<<BB, 512>>>(Wv, bv, Wo, bo, Wc, bc, out);
}

// round 8
// speedup vs baseline: 1.4396x; 1.0318x over previous
#include <cuda_runtime.h>
#include <cuda_bf16.h>
#include <mma.h>
#include <cfloat>

using namespace nvcuda;

#define BB 4
#define NN 8192
#define IND 1024
#define HID 512
#define NHEAD 8
#define TOPK 16
#define NCLS 2
#define HH 91
#define PP (HH*HH)      // 8281
#define NP (PP+1)       // 8282 attention rows (cls + conv out)
#define MM (BB*NN)      // 32768

// ---------------- scratch (static __device__, no allocation) ----------------
__device__ __nv_bfloat16 g_in_bf[(size_t)MM*IND];   // 64 MB
__device__ __nv_bfloat16 g_W_bf[IND*HID];           // 1 MB
__device__ float g_venc[IND];
__device__ float g_scores[MM];
__device__ int   g_topk[BB*TOPK];
__device__ float g_Q[BB*HID];
__device__ __nv_bfloat16 g_x[(size_t)MM*HID];       // relu(x - Q), 32 MB (bf16)
__device__ __nv_bfloat16 g_x2[(size_t)BB*NP*HID];   // cls + conv-out, 33 MB (bf16)
__device__ float g_qvec[BB*HID];
__device__ float g_u[BB*NHEAD*HID];
__device__ float g_qbk[BB*NHEAD];
__device__ float g_logits[BB*NHEAD*NP];
__device__ float g_mx[BB*NHEAD];
__device__ float g_sm[BB*NHEAD];
__device__ float g_w[BB*NHEAD*HID];

// ---------------- fused: v_enc = W_feat @ w_enc  +  W_feat -> bf16 ----------
__global__ void k_venc_wbf(const float* __restrict__ Wf, const float* __restrict__ wenc) {
    int tid = threadIdx.x;
    if (blockIdx.x < 128) {
        __shared__ float we[HID];
        for (int i = tid; i < HID; i += 256) we[i] = wenc[i];
        __syncthreads();
        int warp = tid >> 5, lane = tid & 31;
        int row = blockIdx.x * 8 + warp;
        const float4* r4 = (const float4*)(Wf + (size_t)row*HID);
        float acc = 0.f;
#pragma unroll
        for (int t = 0; t < 4; t++) {
            float4 f = r4[lane + t*32];
            int c = (lane + t*32)*4;
            acc += f.x*we[c] + f.y*we[c+1] + f.z*we[c+2] + f.w*we[c+3];
        }
        for (int o = 16; o; o >>= 1) acc += __shfl_xor_sync(0xffffffffu, acc, o);
        if (lane == 0) g_venc[row] = acc;
    } else {
        int i = (blockIdx.x - 128)*256 + tid;      // float4 index
        float4 f = ((const float4*)Wf)[i];
        __nv_bfloat162 lo = __floats2bfloat162_rn(f.x, f.y);
        __nv_bfloat162 hi = __floats2bfloat162_rn(f.z, f.w);
        uint2 u;
        u.x = *reinterpret_cast<unsigned*>(&lo);
        u.y = *reinterpret_cast<unsigned*>(&hi);
        ((uint2*)g_W_bf)[i] = u;
    }
}

// ---------------- scores (fp32 GEMV) + inputs -> bf16, one pass -------------
__global__ void k_scores(const float* __restrict__ inp) {
    __shared__ float ve[IND];
    int tid = threadIdx.x;
    for (int i = tid; i < IND; i += 256) ve[i] = g_venc[i];
    __syncthreads();
    int warp = tid >> 5, lane = tid & 31;
    int row = blockIdx.x * 8 + warp;
    const float4* r4 = (const float4*)(inp + (size_t)row*IND);
    uint2* dst = (uint2*)(g_in_bf + (size_t)row*IND);
    float acc = 0.f;
#pragma unroll
    for (int t = 0; t < 8; t++) {
        int i = lane + t*32;
        float4 f = r4[i];
        int c = i*4;
        acc += f.x*ve[c] + f.y*ve[c+1] + f.z*ve[c+2] + f.w*ve[c+3];
        __nv_bfloat162 lo = __floats2bfloat162_rn(f.x, f.y);
        __nv_bfloat162 hi = __floats2bfloat162_rn(f.z, f.w);
        uint2 u;
        u.x = *reinterpret_cast<unsigned*>(&lo);
        u.y = *reinterpret_cast<unsigned*>(&hi);
        dst[i] = u;
    }
    for (int o = 16; o; o >>= 1) acc += __shfl_xor_sync(0xffffffffu, acc, o);
    if (lane == 0) g_scores[row] = acc;
}

// ---------------- top-16 per batch + seed g_Q with b_feat -------------------
__global__ void k_topk(const float* __restrict__ bfeat) {
    __shared__ float sv[NN];
    __shared__ float wv[32];
    __shared__ int   wi[32];
    int b = blockIdx.x, tid = threadIdx.x;
    int lane = tid & 31, warp = tid >> 5;
    if (tid < HID) g_Q[b*HID + tid] = bfeat[tid];     // seed for atomic GEMV
    for (int i = tid; i < NN; i += 1024) sv[i] = g_scores[b*NN + i];
    __syncthreads();
    for (int k = 0; k < TOPK; k++) {
        float bv = -FLT_MAX; int bi = 0x7fffffff;
#pragma unroll
        for (int t = 0; t < 8; t++) {
            int i = tid + t*1024;
            float v = sv[i];
            if (v > bv || (v == bv && i < bi)) { bv = v; bi = i; }
        }
#pragma unroll
        for (int o = 16; o; o >>= 1) {
            float ov = __shfl_xor_sync(0xffffffffu, bv, o);
            int   oi = __shfl_xor_sync(0xffffffffu, bi, o);
            if (ov > bv || (ov == bv && oi < bi)) { bv = ov; bi = oi; }
        }
        if (lane == 0) { wv[warp] = bv; wi[warp] = bi; }
        __syncthreads();
        if (warp == 0) {
            float v2 = wv[lane]; int i2 = wi[lane];
#pragma unroll
            for (int o = 16; o; o >>= 1) {
                float ov = __shfl_xor_sync(0xffffffffu, v2, o);
                int   oi = __shfl_xor_sync(0xffffffffu, i2, o);
                if (ov > v2 || (ov == v2 && oi < i2)) { v2 = ov; i2 = oi; }
            }
            if (lane == 0) { g_topk[b*TOPK + k] = i2; sv[i2] = -FLT_MAX; }
        }
        __syncthreads();
    }
}

// ---------------- Q GEMV, K-split 8 ways, atomic combine --------------------
// grid (BB, 8), 1024 threads. g_Q pre-seeded with b_feat in k_topk.
__global__ void k_sumQ(const float* __restrict__ inp, const float* __restrict__ Wf) {
    __shared__ float s[128];
    __shared__ float p2[HID];
    int b = blockIdx.x, ks = blockIdx.y, tid = threadIdx.x;
    if (tid < 128) {                       // suminp for k in [ks*128, ks*128+128)
        int k = ks*128 + tid;
        float acc = 0.f;
#pragma unroll
        for (int t = 0; t < TOPK; t++) {
            int r = g_topk[b*TOPK + t];
            acc += inp[((size_t)b*NN + r)*IND + k];
        }
        s[tid] = acc;
    }
    __syncthreads();
    int col = tid & 511, half = tid >> 9;
    float a = 0.f;
    int i0 = half*64;
#pragma unroll
    for (int i = 0; i < 64; i++)
        a += s[i0 + i]*Wf[(size_t)(ks*128 + i0 + i)*HID + col];
    if (half) p2[col] = a;
    __syncthreads();
    if (!half) atomicAdd(&g_Q[b*HID + col], (a + p2[col]) * (1.f/TOPK));
}

// ---------------- main GEMM (128x64, static smem, bf16 output) --------------
__global__ __launch_bounds__(256) void k_gemm(const float* __restrict__ bfeat) {
    __shared__ __align__(16) unsigned char raw[128*68*4];
    __nv_bfloat16 (*As)[72] = reinterpret_cast<__nv_bfloat16(*)[72]>(raw);
    __nv_bfloat16 (*Bs)[72] = reinterpret_cast<__nv_bfloat16(*)[72]>(raw + 128*72*2);
    float (*Es)[68] = reinterpret_cast<float(*)[68]>(raw);

    int tid = threadIdx.x;
    int m0 = blockIdx.y * 128;
    int n0 = blockIdx.x * 64;
    int b  = m0 >> 13;
    int wid = tid >> 5;
    int wm = wid >> 1, wn = wid & 1;

    int cc = tid & 63;
    float qval = bfeat[n0 + cc] - g_Q[b*HID + n0 + cc];

    wmma::fragment<wmma::accumulator,16,16,16,float> c[2][2];
#pragma unroll
    for (int i = 0; i < 2; i++)
#pragma unroll
        for (int j = 0; j < 2; j++) wmma::fill_fragment(c[i][j], 0.f);

    for (int k0 = 0; k0 < IND; k0 += 64) {
        __syncthreads();
#pragma unroll
        for (int t = 0; t < 4; t++) {           // A tile: 128 x 64
            int idx = tid + t*256;
            int row = idx >> 3, v = idx & 7;
            *(float4*)&As[row][v*8] =
                ((const float4*)(g_in_bf + (size_t)(m0+row)*IND + k0))[v];
        }
#pragma unroll
        for (int t = 0; t < 2; t++) {           // B tile: 64 x 64
            int idx = tid + t*256;
            int row = idx >> 3, v = idx & 7;
            *(float4*)&Bs[row][v*8] =
                ((const float4*)(g_W_bf + (size_t)(k0+row)*HID + n0))[v];
        }
        __syncthreads();
#pragma unroll
        for (int kk = 0; kk < 64; kk += 16) {
            wmma::fragment<wmma::matrix_a,16,16,16,__nv_bfloat16,wmma::row_major> a0, a1;
            wmma::fragment<wmma::matrix_b,16,16,16,__nv_bfloat16,wmma::row_major> b0, b1;
            wmma::load_matrix_sync(a0, &As[wm*32][kk], 72);
            wmma::load_matrix_sync(a1, &As[wm*32+16][kk], 72);
            wmma::load_matrix_sync(b0, &Bs[kk][wn*32], 72);
            wmma::load_matrix_sync(b1, &Bs[kk][wn*32+16], 72);
            wmma::mma_sync(c[0][0], a0, b0, c[0][0]);
            wmma::mma_sync(c[0][1], a0, b1, c[0][1]);
            wmma::mma_sync(c[1][0], a1, b0, c[1][0]);
            wmma::mma_sync(c[1][1], a1, b1, c[1][1]);
        }
    }
    __syncthreads();
#pragma unroll
    for (int i = 0; i < 2; i++)
#pragma unroll
        for (int j = 0; j < 2; j++)
            wmma::store_matrix_sync(&Es[wm*32+i*16][wn*32+j*16], c[i][j], 68,
                                    wmma::mem_row_major);
    __syncthreads();
    int r0 = tid >> 6;
#pragma unroll
    for (int t = 0; t < 32; t++) {
        int r = r0 + t*4;
        g_x[(size_t)(m0 + r)*HID + n0 + cc] =
            __float2bfloat16(fmaxf(Es[r][cc] + qval, 0.f));
    }
}

// ---------------- depthwise 3x3 conv (bf16 in, bf16 out) + cls row ----------
__global__ void k_conv(const float* __restrict__ cw, const float* __restrict__ cb,
                       const float* __restrict__ cls) {
    __shared__ float cws[HID*9];
    __shared__ float cbs[HID];
    int tid = threadIdx.x;   // 512 = channel
    int b = blockIdx.y;
#pragma unroll
    for (int k = 0; k < 9; k++) cws[tid*9 + k] = cw[tid*9 + k];
    cbs[tid] = cb[tid];
    if (blockIdx.x == 0)     // cls token row
        g_x2[(size_t)b*NP*HID + tid] = __float2bfloat16(cls[tid]);
    __syncthreads();
    int p0 = blockIdx.x * 16;
    for (int i = 0; i < 16; i++) {
        int p = p0 + i;
        if (p >= PP) break;
        int y = p / HH, x = p - y*HH;
        float acc = 0.f, center = 0.f;
#pragma unroll
        for (int dy = -1; dy <= 1; dy++) {
            int yy = y + dy; if (yy < 0 || yy >= HH) continue;
#pragma unroll
            for (int dx = -1; dx <= 1; dx++) {
                int xx = x + dx; if (xx < 0 || xx >= HH) continue;
                int pp2 = yy*HH + xx;
                int r = (pp2 < NN) ? pp2 : pp2 - NN;   // wrap padding rows
                float v = __bfloat162float(g_x[((size_t)(b*NN + r))*HID + tid]);
                acc += v * cws[tid*9 + (dy+1)*3 + (dx+1)];
                if (dy == 0 && dx == 0) center = v;
            }
        }
        g_x2[((size_t)b*NP + 1 + p)*HID + tid] = __float2bfloat16(acc + cbs[tid] + center);
    }
}

// ---------------- q projection + per-head key vectors u ---------------------
__global__ void k_attnprep(const float* __restrict__ Wq, const float* __restrict__ bq,
                           const float* __restrict__ Wk, const float* __restrict__ bk) {
    __shared__ float qs[HID];
    int b = blockIdx.x, tid = threadIdx.x;  // 512
    qs[tid] = g_Q[b*HID + tid];
    __syncthreads();
    float acc = bq[tid];
    for (int c = 0; c < HID; c++) acc += qs[c]*Wq[(size_t)c*HID + tid];
    __syncthreads();
    qs[tid] = acc;
    g_qvec[b*HID + tid] = acc;
    __syncthreads();
#pragma unroll
    for (int h = 0; h < NHEAD; h++) {
        float u = 0.f;
        const float* wr = Wk + (size_t)tid*HID + h*64;
        const float* qh = qs + h*64;
        for (int d = 0; d < 64; d++) u += wr[d]*qh[d];
        g_u[(b*NHEAD + h)*HID + tid] = u;
    }
    if (tid < NHEAD) {
        float qb = 0.f;
        for (int d = 0; d < 64; d++) qb += bk[tid*64 + d]*qs[tid*64 + d];
        g_qbk[b*NHEAD + tid] = qb;
    }
    for (int t = tid; t < NHEAD*HID; t += 512) g_w[b*NHEAD*HID + t] = 0.f;
}

// ---------------- logits over 8282 keys (bf16 x2, 8 heads per pass) ---------
__global__ void k_logits() {
    __shared__ float us[NHEAD*HID];
    __shared__ float qb[NHEAD];
    int tid = threadIdx.x;  // 256
    int b = blockIdx.y;
    for (int i = tid; i < NHEAD*HID; i += 256) us[i] = g_u[b*NHEAD*HID + i];
    if (tid < NHEAD) qb[tid] = g_qbk[b*NHEAD + tid];
    __syncthreads();
    int warp = tid >> 5, lane = tid & 31;
    const float RS = 0.0441941738241592f;   // 1/sqrt(512)
    for (int it = 0; it < 4; it++) {
        int n = blockIdx.x*32 + warp*4 + it;
        if (n >= NP) break;
        const uint4* row = (const uint4*)(g_x2 + ((size_t)b*NP + n)*HID);  // 64 x uint4
        float acc[NHEAD] = {0,0,0,0,0,0,0,0};
#pragma unroll
        for (int t = 0; t < 2; t++) {
            int i = lane + t*32;
            uint4 u4 = row[i];
            int c = i*8;
            float2 f0 = __bfloat1622float2(*reinterpret_cast<__nv_bfloat162*>(&u4.x));
            float2 f1 = __bfloat1622float2(*reinterpret_cast<__nv_bfloat162*>(&u4.y));
            float2 f2 = __bfloat1622float2(*reinterpret_cast<__nv_bfloat162*>(&u4.z));
            float2 f3 = __bfloat1622float2(*reinterpret_cast<__nv_bfloat162*>(&u4.w));
#pragma unroll
            for (int h = 0; h < NHEAD; h++) {
                const float* uh = us + h*HID + c;
                acc[h] += f0.x*uh[0] + f0.y*uh[1] + f1.x*uh[2] + f1.y*uh[3]
                        + f2.x*uh[4] + f2.y*uh[5] + f3.x*uh[6] + f3.y*uh[7];
            }
        }
#pragma unroll
        for (int h = 0; h < NHEAD; h++)
            for (int o = 16; o; o >>= 1) acc[h] += __shfl_xor_sync(0xffffffffu, acc[h], o);
        if (lane == 0) {
#pragma unroll
            for (int h = 0; h < NHEAD; h++)
                g_logits[((size_t)(b*NHEAD + h))*NP + n] = (acc[h] + qb[h]) * RS;
        }
    }
}

// ---------------- softmax stats (max, sumexp) per (b,h) ---------------------
__global__ void k_softmax() {
    __shared__ float red[256];
    int bh = blockIdx.x, tid = threadIdx.x;
    const float* l = g_logits + (size_t)bh*NP;
    float m = -3.4e38f;
    for (int i = tid; i < NP; i += 256) m = fmaxf(m, l[i]);
    red[tid] = m; __syncthreads();
    for (int s = 128; s; s >>= 1) { if (tid < s) red[tid] = fmaxf(red[tid], red[tid+s]); __syncthreads(); }
    m = red[0]; __syncthreads();
    float sum = 0.f;
    for (int i = tid; i < NP; i += 256) sum += expf(l[i] - m);
    red[tid] = sum; __syncthreads();
    for (int s = 128; s; s >>= 1) { if (tid < s) red[tid] += red[tid+s]; __syncthreads(); }
    if (tid == 0) { g_mx[bh] = m; g_sm[bh] = red[0]; }
}

// ---------------- weighted sums w[b,h,:] = sum_n A x2[n,:] (bf16 x2) --------
#define WCH 130
__global__ void k_wsum() {
    __shared__ float as[NHEAD*WCH];
    int tid = threadIdx.x;   // 512 = channel
    int b = blockIdx.y;
    int base = blockIdx.x * WCH;
    for (int idx = tid; idx < NHEAD*WCH; idx += 512) {
        int h = idx / WCH, i = idx - h*WCH;
        int n = base + i;
        float a = 0.f;
        if (n < NP) {
            int bh = b*NHEAD + h;
            a = expf(g_logits[(size_t)bh*NP + n] - g_mx[bh]) / g_sm[bh];
        }
        as[idx] = a;
    }
    __syncthreads();
    float w[NHEAD] = {0,0,0,0,0,0,0,0};
    for (int i = 0; i < WCH; i++) {
        int n = base + i;
        if (n >= NP) break;
        float v = __bfloat162float(g_x2[((size_t)b*NP + n)*HID + tid]);
#pragma unroll
        for (int h = 0; h < NHEAD; h++) w[h] += as[h*WCH + i]*v;
    }
#pragma unroll
    for (int h = 0; h < NHEAD; h++)
        atomicAdd(&g_w[(b*NHEAD + h)*HID + tid], w[h]);
}

// ---------------- finale: O = q + w@Wv + bv; O += relu(O@Wo+bo); out=O@Wc+bc
__global__ void k_finale(const float* __restrict__ Wv, const float* __restrict__ bv,
                         const float* __restrict__ Wo, const float* __restrict__ bo,
                         const float* __restrict__ Wc, const float* __restrict__ bc,
                         float* __restrict__ out) {
    __shared__ float ws[NHEAD*HID];
    __shared__ float Ov[HID];
    __shared__ float red[HID];
    int b = blockIdx.x, tid = threadIdx.x;  // 512
    for (int i = tid; i < NHEAD*HID; i += 512) ws[i] = g_w[b*NHEAD*HID + i];
    __syncthreads();
    int h = tid >> 6;
    float acc = bv[tid] + g_qvec[b*HID + tid];
    const float* wh = ws + h*HID;
    for (int c = 0; c < HID; c++) acc += wh[c]*Wv[(size_t)c*HID + tid];
    Ov[tid] = acc;
    __syncthreads();
    float t2 = bo[tid];
    for (int c = 0; c < HID; c++) t2 += Ov[c]*Wo[(size_t)c*HID + tid];
    __syncthreads();
    Ov[tid] = Ov[tid] + fmaxf(t2, 0.f);
    __syncthreads();
    for (int j = 0; j < NCLS; j++) {
        red[tid] = Ov[tid]*Wc[tid*NCLS + j];
        __syncthreads();
        for (int s = 256; s; s >>= 1) { if (tid < s) red[tid] += red[tid+s]; __syncthreads(); }
        if (tid == 0) out[b*NCLS + j] = red[0] + bc[j];
        __syncthreads();
    }
}

// ---------------------------------------------------------------------------
extern "C" void kernel_launch(void* const* d_in, const int* in_sizes, int n_in,
                              void* d_out, int out_size) {
    const float* inputs  = (const float*)d_in[0];
    const float* W_feat  = (const float*)d_in[1];
    const float* b_feat  = (const float*)d_in[2];
    const float* w_enc   = (const float*)d_in[3];
    // d_in[4] = b_enc: uniform shift before sigmoid -> does not affect top-k
    const float* cls_tok = (const float*)d_in[5];
    const float* conv_w  = (const float*)d_in[6];
    const float* conv_b  = (const float*)d_in[7];
    const float* Wq = (const float*)d_in[8];
    const float* bq = (const float*)d_in[9];
    const float* Wk = (const float*)d_in[10];
    const float* bk = (const float*)d_in[11];
    const float* Wv = (const float*)d_in[12];
    const float* bv = (const float*)d_in[13];
    const float* Wo = (const float*)d_in[14];
    const float* bo = (const float*)d_in[15];
    const float* Wc = (const float*)d_in[16];
    const float* bc = (const float*)d_in[17];
    float* out = (float*)d_out;

    k_venc_wbf<<<128 + IND*HID/4/256, 256>>>(W_feat, w_enc);
    k_scores<<<MM/8, 256>>>(inputs);
    k_topk  <<<BB, 1024>>>(b_feat);
    k_sumQ  <<<dim3(BB, 8), 1024>>>(inputs, W_feat);
    k_gemm  <<<dim3(HID/64, MM/128), 256>>>(b_feat);
    k_conv  <<<dim3((PP+15)/16, BB), 512>>>(conv_w, conv_b, cls_tok);
    k_attnprep<<<BB, 512>>>(Wq, bq, Wk, bk);
    k_logits<<<dim3((NP+31)/32, BB), 256>>>();
    k_softmax<<<BB*NHEAD, 256>>>();
    k_wsum  <<<dim3((NP+WCH-1)/WCH, BB), 512>>>();
    k_finale<<<BB, 512>>>(Wv, bv, Wo, bo, Wc, bc, out);
}

// round 15
// speedup vs baseline: 1.5247x; 1.0591x over previous
#include <cuda_runtime.h>
#include <cuda_bf16.h>
#include <cstdint>
#include <cfloat>

#define BB 4
#define NN 8192
#define IND 1024
#define HID 512
#define NHEAD 8
#define TOPK 16
#define NCLS 2
#define HH 91
#define PP (HH*HH)      // 8281
#define NP (PP+1)       // 8282 attention rows (cls + conv out)
#define MM (BB*NN)      // 32768

// ---------------- scratch (static __device__, no allocation) ----------------
__device__ __nv_bfloat16 g_in_bf[(size_t)MM*IND];   // 64 MB
__device__ __nv_bfloat16 g_Wt_bf[(size_t)HID*IND];  // W transposed [N][K], 1 MB
__device__ float g_venc[IND];
__device__ float g_scores[MM];
__device__ float g_Q[BB*HID];
__device__ __nv_bfloat16 g_x[(size_t)MM*HID];       // relu(x - Q), 32 MB (bf16)
__device__ __nv_bfloat16 g_x2[(size_t)BB*NP*HID];   // cls + conv-out, 33 MB (bf16)
__device__ float g_qvec[BB*HID];
__device__ float g_u[BB*NHEAD*HID];
__device__ float g_qbk[BB*NHEAD];
__device__ float g_logits[BB*NHEAD*NP];
__device__ float g_mx[BB*NHEAD];
__device__ float g_sm[BB*NHEAD];
__device__ float g_w[BB*NHEAD*HID];

__device__ __forceinline__ uint32_t smem_u32(const void* p) {
    return (uint32_t)__cvta_generic_to_shared(p);
}
__device__ __forceinline__ void ldm_x4(uint32_t& r0, uint32_t& r1, uint32_t& r2,
                                       uint32_t& r3, uint32_t addr) {
    asm volatile("ldmatrix.sync.aligned.m8n8.x4.shared.b16 {%0,%1,%2,%3}, [%4];"
                 : "=r"(r0), "=r"(r1), "=r"(r2), "=r"(r3) : "r"(addr));
}
__device__ __forceinline__ void mma16816(float* c, uint32_t a0, uint32_t a1,
                                         uint32_t a2, uint32_t a3,
                                         uint32_t b0, uint32_t b1) {
    asm volatile(
        "mma.sync.aligned.m16n8k16.row.col.f32.bf16.bf16.f32 "
        "{%0,%1,%2,%3}, {%4,%5,%6,%7}, {%8,%9}, {%0,%1,%2,%3};"
        : "+f"(c[0]), "+f"(c[1]), "+f"(c[2]), "+f"(c[3])
        : "r"(a0), "r"(a1), "r"(a2), "r"(a3), "r"(b0), "r"(b1));
}

// ---------------- prep: v_enc GEMV + W->Wt bf16 transpose + seed g_Q --------
__global__ void k_prep(const float* __restrict__ Wf, const float* __restrict__ wenc,
                       const float* __restrict__ bfeat) {
    int tid = threadIdx.x;
    int gs = blockIdx.x*256 + tid;
    if (gs < BB*HID) g_Q[gs] = bfeat[gs & (HID-1)];   // seed for atomic GEMV
    if (blockIdx.x < 128) {
        __shared__ float we[HID];
        for (int i = tid; i < HID; i += 256) we[i] = wenc[i];
        __syncthreads();
        int warp = tid >> 5, lane = tid & 31;
        int row = blockIdx.x * 8 + warp;
        const float4* r4 = (const float4*)(Wf + (size_t)row*HID);
        float acc = 0.f;
#pragma unroll
        for (int t = 0; t < 4; t++) {
            float4 f = r4[lane + t*32];
            int c = (lane + t*32)*4;
            acc += f.x*we[c] + f.y*we[c+1] + f.z*we[c+2] + f.w*we[c+3];
        }
        for (int o = 16; o; o >>= 1) acc += __shfl_xor_sync(0xffffffffu, acc, o);
        if (lane == 0) g_venc[row] = acc;
    } else {
        // transpose W (1024x512 f32) -> Wt (512x1024 bf16), 32x32 tiles
        __shared__ float ts[32][33];
        int t = blockIdx.x - 128;            // 512 tiles: 32 (k) x 16 (n)
        int k0 = (t & 31) * 32, n0 = (t >> 5) * 32;
        int tx = tid & 31, ty = tid >> 5;    // 32 x 8
#pragma unroll
        for (int r = 0; r < 4; r++) {
            int k = k0 + ty + r*8;
            ts[ty + r*8][tx] = Wf[(size_t)k*HID + n0 + tx];
        }
        __syncthreads();
#pragma unroll
        for (int r = 0; r < 4; r++) {
            int n = n0 + ty + r*8;
            g_Wt_bf[(size_t)n*IND + k0 + tx] = __float2bfloat16(ts[tx][ty + r*8]);
        }
    }
}

// ---------------- scores (fp32 GEMV) + inputs -> bf16, one pass -------------
__global__ void k_scores(const float* __restrict__ inp) {
    __shared__ float ve[IND];
    int tid = threadIdx.x;
    for (int i = tid; i < IND; i += 256) ve[i] = g_venc[i];
    __syncthreads();
    int warp = tid >> 5, lane = tid & 31;
    int row = blockIdx.x * 8 + warp;
    const float4* r4 = (const float4*)(inp + (size_t)row*IND);
    uint2* dst = (uint2*)(g_in_bf + (size_t)row*IND);
    float acc = 0.f;
#pragma unroll
    for (int t = 0; t < 8; t++) {
        int i = lane + t*32;
        float4 f = r4[i];
        int c = i*4;
        acc += f.x*ve[c] + f.y*ve[c+1] + f.z*ve[c+2] + f.w*ve[c+3];
        __nv_bfloat162 lo = __floats2bfloat162_rn(f.x, f.y);
        __nv_bfloat162 hi = __floats2bfloat162_rn(f.z, f.w);
        uint2 u;
        u.x = *reinterpret_cast<unsigned*>(&lo);
        u.y = *reinterpret_cast<unsigned*>(&hi);
        dst[i] = u;
    }
    for (int o = 16; o; o >>= 1) acc += __shfl_xor_sync(0xffffffffu, acc, o);
    if (lane == 0) g_scores[row] = acc;
}

// ---------------- fused top-16 (redundant per K-slice) + Q GEMV slice -------
// grid (BB, 8), 1024 threads. g_Q pre-seeded with b_feat in k_prep.
__global__ void k_topkQ(const float* __restrict__ inp, const float* __restrict__ Wf) {
    __shared__ float sv[NN];
    __shared__ float wv[32];
    __shared__ int   wi[32];
    __shared__ int   ti[TOPK];
    __shared__ float s[128];
    __shared__ float p2[HID];
    int b = blockIdx.x, ks = blockIdx.y, tid = threadIdx.x;
    int lane = tid & 31, warp = tid >> 5;
    for (int i = tid; i < NN; i += 1024) sv[i] = g_scores[b*NN + i];
    __syncthreads();
    for (int k = 0; k < TOPK; k++) {
        float bv = -FLT_MAX; int bi = 0x7fffffff;
#pragma unroll
        for (int t = 0; t < 8; t++) {
            int i = tid + t*1024;
            float v = sv[i];
            if (v > bv || (v == bv && i < bi)) { bv = v; bi = i; }
        }
#pragma unroll
        for (int o = 16; o; o >>= 1) {
            float ov = __shfl_xor_sync(0xffffffffu, bv, o);
            int   oi = __shfl_xor_sync(0xffffffffu, bi, o);
            if (ov > bv || (ov == bv && oi < bi)) { bv = ov; bi = oi; }
        }
        if (lane == 0) { wv[warp] = bv; wi[warp] = bi; }
        __syncthreads();
        if (warp == 0) {
            float v2 = wv[lane]; int i2 = wi[lane];
#pragma unroll
            for (int o = 16; o; o >>= 1) {
                float ov = __shfl_xor_sync(0xffffffffu, v2, o);
                int   oi = __shfl_xor_sync(0xffffffffu, i2, o);
                if (ov > v2 || (ov == v2 && oi < i2)) { v2 = ov; i2 = oi; }
            }
            if (lane == 0) { ti[k] = i2; sv[i2] = -FLT_MAX; }
        }
        __syncthreads();
    }
    // Q GEMV for K-slice [ks*128, ks*128+128)
    if (tid < 128) {
        int k = ks*128 + tid;
        float acc = 0.f;
#pragma unroll
        for (int t = 0; t < TOPK; t++)
            acc += inp[((size_t)b*NN + ti[t])*IND + k];
        s[tid] = acc;
    }
    __syncthreads();
    int col = tid & 511, half = tid >> 9;
    float a = 0.f;
    int i0 = half*64;
#pragma unroll
    for (int i = 0; i < 64; i++)
        a += s[i0 + i]*Wf[(size_t)(ks*128 + i0 + i)*HID + col];
    if (half) p2[col] = a;
    __syncthreads();
    if (!half) atomicAdd(&g_Q[b*HID + col], (a + p2[col]) * (1.f/TOPK));
}

// ---------------- main GEMM: mma.sync m16n8k16 + swizzled ldmatrix ----------
// CTA tile 128x64, K-step 64, 256 threads (8 warps as 4x2, warp tile 32x32)
__global__ __launch_bounds__(256) void k_gemm(const float* __restrict__ bfeat) {
    __shared__ __align__(16) unsigned char raw[128*68*4];   // 34816 B
    __nv_bfloat16* As = (__nv_bfloat16*)raw;                // [128][64] swizzled
    __nv_bfloat16* Bs = (__nv_bfloat16*)(raw + 16384);      // [64][64] swizzled
    float (*Es)[68] = reinterpret_cast<float(*)[68]>(raw);

    int tid = threadIdx.x, wid = tid >> 5, lane = tid & 31;
    int m0 = blockIdx.y * 128, n0 = blockIdx.x * 64;
    int b = m0 >> 13;
    int wm = wid >> 1, wn = wid & 1;
    uint32_t As_u = smem_u32(As), Bs_u = smem_u32(Bs);

    const __nv_bfloat16* Ab = g_in_bf + (size_t)m0*IND;
    const __nv_bfloat16* Bb = g_Wt_bf + (size_t)n0*IND;

    int lrow = lane & 15, lcb = lane >> 4;
    float c[2][4][4] = {};

    for (int kt = 0; kt < 16; kt++) {
        int k0 = kt*64;
        __syncthreads();
#pragma unroll
        for (int i = 0; i < 4; i++) {              // A: 128x64 (1024 16B chunks)
            int id = tid + i*256;
            int row = id >> 3, c16 = id & 7;
            uint32_t bo = row*128 + c16*16;
            uint32_t sw = bo ^ ((row & 7) << 4);
            *(uint4*)((char*)As + sw) = *(const uint4*)(Ab + (size_t)row*IND + k0 + c16*8);
        }
#pragma unroll
        for (int i = 0; i < 2; i++) {              // B: 64x64 (512 chunks)
            int id = tid + i*256;
            int row = id >> 3, c16 = id & 7;
            uint32_t bo = row*128 + c16*16;
            uint32_t sw = bo ^ ((row & 7) << 4);
            *(uint4*)((char*)Bs + sw) = *(const uint4*)(Bb + (size_t)row*IND + k0 + c16*8);
        }
        __syncthreads();
#pragma unroll
        for (int kk = 0; kk < 4; kk++) {
            int colb = kk*32 + lcb*16;
            uint32_t a[2][4];
#pragma unroll
            for (int i = 0; i < 2; i++) {
                int row = wm*32 + i*16 + lrow;
                uint32_t bo = row*128 + colb;
                ldm_x4(a[i][0], a[i][1], a[i][2], a[i][3],
                       As_u + (bo ^ ((row & 7) << 4)));
            }
            uint32_t bf[4][2];
#pragma unroll
            for (int j = 0; j < 2; j++) {
                int row = wn*32 + j*16 + lrow;
                uint32_t bo = row*128 + colb;
                uint32_t r0, r1, r2, r3;
                ldm_x4(r0, r1, r2, r3, Bs_u + (bo ^ ((row & 7) << 4)));
                bf[j*2][0] = r0; bf[j*2][1] = r2;
                bf[j*2+1][0] = r1; bf[j*2+1][1] = r3;
            }
#pragma unroll
            for (int i = 0; i < 2; i++)
#pragma unroll
                for (int nb = 0; nb < 4; nb++)
                    mma16816(c[i][nb], a[i][0], a[i][1], a[i][2], a[i][3],
                             bf[nb][0], bf[nb][1]);
        }
    }
    __syncthreads();
    // stage accumulators to smem for coalesced epilogue
    int r4 = lane >> 2, cp = (lane & 3)*2;
#pragma unroll
    for (int i = 0; i < 2; i++)
#pragma unroll
        for (int nb = 0; nb < 4; nb++) {
            int rr = wm*32 + i*16 + r4;
            int cc = wn*32 + nb*8 + cp;
            Es[rr][cc]     = c[i][nb][0];
            Es[rr][cc+1]   = c[i][nb][1];
            Es[rr+8][cc]   = c[i][nb][2];
            Es[rr+8][cc+1] = c[i][nb][3];
        }
    __syncthreads();
    int ccc = tid & 63, rb = tid >> 6;
    float qval = bfeat[n0 + ccc] - g_Q[b*HID + n0 + ccc];
#pragma unroll
    for (int t = 0; t < 32; t++) {
        int r = rb + t*4;
        g_x[(size_t)(m0 + r)*HID + n0 + ccc] =
            __float2bfloat16(fmaxf(Es[r][ccc] + qval, 0.f));
    }
}

// ---------------- depthwise 3x3 conv (bf16 in, bf16 out) + cls row ----------
__global__ void k_conv(const float* __restrict__ cw, const float* __restrict__ cb,
                       const float* __restrict__ cls) {
    __shared__ float cws[HID*9];
    __shared__ float cbs[HID];
    int tid = threadIdx.x;   // 512 = channel
    int b = blockIdx.y;
#pragma unroll
    for (int k = 0; k < 9; k++) cws[tid*9 + k] = cw[tid*9 + k];
    cbs[tid] = cb[tid];
    if (blockIdx.x == 0)     // cls token row
        g_x2[(size_t)b*NP*HID + tid] = __float2bfloat16(cls[tid]);
    __syncthreads();
    int p0 = blockIdx.x * 16;
    for (int i = 0; i < 16; i++) {
        int p = p0 + i;
        if (p >= PP) break;
        int y = p / HH, x = p - y*HH;
        float acc = 0.f, center = 0.f;
#pragma unroll
        for (int dy = -1; dy <= 1; dy++) {
            int yy = y + dy; if (yy < 0 || yy >= HH) continue;
#pragma unroll
            for (int dx = -1; dx <= 1; dx++) {
                int xx = x + dx; if (xx < 0 || xx >= HH) continue;
                int pp2 = yy*HH + xx;
                int r = (pp2 < NN) ? pp2 : pp2 - NN;   // wrap padding rows
                float v = __bfloat162float(g_x[((size_t)(b*NN + r))*HID + tid]);
                acc += v * cws[tid*9 + (dy+1)*3 + (dx+1)];
                if (dy == 0 && dx == 0) center = v;
            }
        }
        g_x2[((size_t)b*NP + 1 + p)*HID + tid] = __float2bfloat16(acc + cbs[tid] + center);
    }
}

// ---------------- q projection + per-head key vectors u ---------------------
__global__ void k_attnprep(const float* __restrict__ Wq, const float* __restrict__ bq,
                           const float* __restrict__ Wk, const float* __restrict__ bk) {
    __shared__ float qs[HID];
    int b = blockIdx.x, tid = threadIdx.x;  // 512
    qs[tid] = g_Q[b*HID + tid];
    __syncthreads();
    float acc = bq[tid];
    for (int c = 0; c < HID; c++) acc += qs[c]*Wq[(size_t)c*HID + tid];
    __syncthreads();
    qs[tid] = acc;
    g_qvec[b*HID + tid] = acc;
    __syncthreads();
#pragma unroll
    for (int h = 0; h < NHEAD; h++) {
        float u = 0.f;
        const float* wr = Wk + (size_t)tid*HID + h*64;
        const float* qh = qs + h*64;
        for (int d = 0; d < 64; d++) u += wr[d]*qh[d];
        g_u[(b*NHEAD + h)*HID + tid] = u;
    }
    if (tid < NHEAD) {
        float qb = 0.f;
        for (int d = 0; d < 64; d++) qb += bk[tid*64 + d]*qs[tid*64 + d];
        g_qbk[b*NHEAD + tid] = qb;
    }
    for (int t = tid; t < NHEAD*HID; t += 512) g_w[b*NHEAD*HID + t] = 0.f;
}

// ---------------- logits over 8282 keys (bf16 x2, 8 heads per pass) ---------
__global__ void k_logits() {
    __shared__ float us[NHEAD*HID];
    __shared__ float qb[NHEAD];
    int tid = threadIdx.x;  // 256
    int b = blockIdx.y;
    for (int i = tid; i < NHEAD*HID; i += 256) us[i] = g_u[b*NHEAD*HID + i];
    if (tid < NHEAD) qb[tid] = g_qbk[b*NHEAD + tid];
    __syncthreads();
    int warp = tid >> 5, lane = tid & 31;
    const float RS = 0.0441941738241592f;   // 1/sqrt(512)
    for (int it = 0; it < 4; it++) {
        int n = blockIdx.x*32 + warp*4 + it;
        if (n >= NP) break;
        const uint4* row = (const uint4*)(g_x2 + ((size_t)b*NP + n)*HID);  // 64 x uint4
        float acc[NHEAD] = {0,0,0,0,0,0,0,0};
#pragma unroll
        for (int t = 0; t < 2; t++) {
            int i = lane + t*32;
            uint4 u4 = row[i];
            int c = i*8;
            float2 f0 = __bfloat1622float2(*reinterpret_cast<__nv_bfloat162*>(&u4.x));
            float2 f1 = __bfloat1622float2(*reinterpret_cast<__nv_bfloat162*>(&u4.y));
            float2 f2 = __bfloat1622float2(*reinterpret_cast<__nv_bfloat162*>(&u4.z));
            float2 f3 = __bfloat1622float2(*reinterpret_cast<__nv_bfloat162*>(&u4.w));
#pragma unroll
            for (int h = 0; h < NHEAD; h++) {
                const float* uh = us + h*HID + c;
                acc[h] += f0.x*uh[0] + f0.y*uh[1] + f1.x*uh[2] + f1.y*uh[3]
                        + f2.x*uh[4] + f2.y*uh[5] + f3.x*uh[6] + f3.y*uh[7];
            }
        }
#pragma unroll
        for (int h = 0; h < NHEAD; h++)
            for (int o = 16; o; o >>= 1) acc[h] += __shfl_xor_sync(0xffffffffu, acc[h], o);
        if (lane == 0) {
#pragma unroll
            for (int h = 0; h < NHEAD; h++)
                g_logits[((size_t)(b*NHEAD + h))*NP + n] = (acc[h] + qb[h]) * RS;
        }
    }
}

// ---------------- softmax stats (max, sumexp) per (b,h) ---------------------
__global__ void k_softmax() {
    __shared__ float red[256];
    int bh = blockIdx.x, tid = threadIdx.x;
    const float* l = g_logits + (size_t)bh*NP;
    float m = -3.4e38f;
    for (int i = tid; i < NP; i += 256) m = fmaxf(m, l[i]);
    red[tid] = m; __syncthreads();
    for (int s = 128; s; s >>= 1) { if (tid < s) red[tid] = fmaxf(red[tid], red[tid+s]); __syncthreads(); }
    m = red[0]; __syncthreads();
    float sum = 0.f;
    for (int i = tid; i < NP; i += 256) sum += expf(l[i] - m);
    red[tid] = sum; __syncthreads();
    for (int s = 128; s; s >>= 1) { if (tid < s) red[tid] += red[tid+s]; __syncthreads(); }
    if (tid == 0) { g_mx[bh] = m; g_sm[bh] = red[0]; }
}

// ---------------- weighted sums w[b,h,:] = sum_n A x2[n,:] (bf16 x2) --------
#define WCH 130
__global__ void k_wsum() {
    __shared__ float as[NHEAD*WCH];
    int tid = threadIdx.x;   // 512 = channel
    int b = blockIdx.y;
    int base = blockIdx.x * WCH;
    for (int idx = tid; idx < NHEAD*WCH; idx += 512) {
        int h = idx / WCH, i = idx - h*WCH;
        int n = base + i;
        float a = 0.f;
        if (n < NP) {
            int bh = b*NHEAD + h;
            a = expf(g_logits[(size_t)bh*NP + n] - g_mx[bh]) / g_sm[bh];
        }
        as[idx] = a;
    }
    __syncthreads();
    float w[NHEAD] = {0,0,0,0,0,0,0,0};
    for (int i = 0; i < WCH; i++) {
        int n = base + i;
        if (n >= NP) break;
        float v = __bfloat162float(g_x2[((size_t)b*NP + n)*HID + tid]);
#pragma unroll
        for (int h = 0; h < NHEAD; h++) w[h] += as[h*WCH + i]*v;
    }
#pragma unroll
    for (int h = 0; h < NHEAD; h++)
        atomicAdd(&g_w[(b*NHEAD + h)*HID + tid], w[h]);
}

// ---------------- finale: O = q + w@Wv + bv; O += relu(O@Wo+bo); out=O@Wc+bc
__global__ void k_finale(const float* __restrict__ Wv, const float* __restrict__ bv,
                         const float* __restrict__ Wo, const float* __restrict__ bo,
                         const float* __restrict__ Wc, const float* __restrict__ bc,
                         float* __restrict__ out) {
    __shared__ float ws[NHEAD*HID];
    __shared__ float Ov[HID];
    __shared__ float red[HID];
    int b = blockIdx.x, tid = threadIdx.x;  // 512
    for (int i = tid; i < NHEAD*HID; i += 512) ws[i] = g_w[b*NHEAD*HID + i];
    __syncthreads();
    int h = tid >> 6;
    float acc = bv[tid] + g_qvec[b*HID + tid];
    const float* wh = ws + h*HID;
    for (int c = 0; c < HID; c++) acc += wh[c]*Wv[(size_t)c*HID + tid];
    Ov[tid] = acc;
    __syncthreads();
    float t2 = bo[tid];
    for (int c = 0; c < HID; c++) t2 += Ov[c]*Wo[(size_t)c*HID + tid];
    __syncthreads();
    Ov[tid] = Ov[tid] + fmaxf(t2, 0.f);
    __syncthreads();
    for (int j = 0; j < NCLS; j++) {
        red[tid] = Ov[tid]*Wc[tid*NCLS + j];
        __syncthreads();
        for (int s = 256; s; s >>= 1) { if (tid < s) red[tid] += red[tid+s]; __syncthreads(); }
        if (tid == 0) out[b*NCLS + j] = red[0] + bc[j];
        __syncthreads();
    }
}

// ---------------------------------------------------------------------------
extern "C" void kernel_launch(void* const* d_in, const int* in_sizes, int n_in,
                              void* d_out, int out_size) {
    const float* inputs  = (const float*)d_in[0];
    const float* W_feat  = (const float*)d_in[1];
    const float* b_feat  = (const float*)d_in[2];
    const float* w_enc   = (const float*)d_in[3];
    // d_in[4] = b_enc: uniform shift before sigmoid -> does not affect top-k
    const float* cls_tok = (const float*)d_in[5];
    const float* conv_w  = (const float*)d_in[6];
    const float* conv_b  = (const float*)d_in[7];
    const float* Wq = (const float*)d_in[8];
    const float* bq = (const float*)d_in[9];
    const float* Wk = (const float*)d_in[10];
    const float* bk = (const float*)d_in[11];
    const float* Wv = (const float*)d_in[12];
    const float* bv = (const float*)d_in[13];
    const float* Wo = (const float*)d_in[14];
    const float* bo = (const float*)d_in[15];
    const float* Wc = (const float*)d_in[16];
    const float* bc = (const float*)d_in[17];
    float* out = (float*)d_out;

    k_prep  <<<128 + 512, 256>>>(W_feat, w_enc, b_feat);
    k_scores<<<MM/8, 256>>>(inputs);
    k_topkQ <<<dim3(BB, 8), 1024>>>(inputs, W_feat);
    k_gemm  <<<dim3(HID/64, MM/128), 256>>>(b_feat);
    k_conv  <<<dim3((PP+15)/16, BB), 512>>>(conv_w, conv_b, cls_tok);
    k_attnprep<<<BB, 512>>>(Wq, bq, Wk, bk);
    k_logits<<<dim3((NP+31)/32, BB), 256>>>();
    k_softmax<<<BB*NHEAD, 256>>>();
    k_wsum  <<<dim3((NP+WCH-1)/WCH, BB), 512>>>();
    k_finale<<<BB, 512>>>(Wv, bv, Wo, bo, Wc, bc, out);
}

// round 17
// speedup vs baseline: 2.0227x; 1.3267x over previous
#include <cuda_runtime.h>
#include <cuda_bf16.h>
#include <cstdint>
#include <cfloat>

#define BB 4
#define NN 8192
#define IND 1024
#define HID 512
#define NHEAD 8
#define TOPK 16
#define NCLS 2
#define HH 91
#define PP (HH*HH)      // 8281
#define NP (PP+1)       // 8282 attention rows (cls + conv out)
#define MM (BB*NN)      // 32768

// ---------------- scratch (static __device__, no allocation) ----------------
__device__ __nv_bfloat16 g_in_bf[(size_t)MM*IND];   // 64 MB
__device__ __nv_bfloat16 g_Wt_bf[(size_t)HID*IND];  // W transposed [N][K], 1 MB
__device__ float g_WkT[(size_t)HID*HID];            // Wk transposed [d][c], 1 MB
__device__ float g_venc[IND];
__device__ float g_scores[MM];
__device__ float g_Q[BB*HID];
__device__ __nv_bfloat16 g_x[(size_t)MM*HID];       // relu(x - Q), 32 MB (bf16)
__device__ __nv_bfloat16 g_x2[(size_t)BB*NP*HID];   // cls + conv-out, 33 MB (bf16)
__device__ float g_qvec[BB*HID];                    // seeded bq, atomic GEMV
__device__ float g_u[BB*NHEAD*HID];
__device__ float g_qbk[BB*NHEAD];
__device__ float g_logits[BB*NHEAD*NP];
__device__ float g_mx[BB*NHEAD];
__device__ float g_sm[BB*NHEAD];
__device__ float g_w[BB*NHEAD*HID];
__device__ float g_Ov[BB*HID];                      // seeded bv, atomic GEMV
__device__ float g_t2[BB*HID];                      // seeded bo, atomic GEMV

__device__ __forceinline__ uint32_t smem_u32(const void* p) {
    return (uint32_t)__cvta_generic_to_shared(p);
}
__device__ __forceinline__ void ldm_x4(uint32_t& r0, uint32_t& r1, uint32_t& r2,
                                       uint32_t& r3, uint32_t addr) {
    asm volatile("ldmatrix.sync.aligned.m8n8.x4.shared.b16 {%0,%1,%2,%3}, [%4];"
                 : "=r"(r0), "=r"(r1), "=r"(r2), "=r"(r3) : "r"(addr));
}
__device__ __forceinline__ void mma16816(float* c, uint32_t a0, uint32_t a1,
                                         uint32_t a2, uint32_t a3,
                                         uint32_t b0, uint32_t b1) {
    asm volatile(
        "mma.sync.aligned.m16n8k16.row.col.f32.bf16.bf16.f32 "
        "{%0,%1,%2,%3}, {%4,%5,%6,%7}, {%8,%9}, {%0,%1,%2,%3};"
        : "+f"(c[0]), "+f"(c[1]), "+f"(c[2]), "+f"(c[3])
        : "r"(a0), "r"(a1), "r"(a2), "r"(a3), "r"(b0), "r"(b1));
}

// ---------------- prep: venc GEMV + Wf->Wt bf16 + Wk->WkT + seeds -----------
__global__ void k_prep(const float* __restrict__ Wf, const float* __restrict__ wenc,
                       const float* __restrict__ bfeat, const float* __restrict__ bq,
                       const float* __restrict__ bv, const float* __restrict__ bo,
                       const float* __restrict__ Wk) {
    int tid = threadIdx.x;
    int gs = blockIdx.x*256 + tid;
    if (gs < BB*HID) {
        int c = gs & (HID-1);
        g_Q[gs]    = bfeat[c];
        g_qvec[gs] = bq[c];
        g_Ov[gs]   = bv[c];
        g_t2[gs]   = bo[c];
    }
    if (gs < BB*NHEAD*HID) g_w[gs] = 0.f;

    if (blockIdx.x < 128) {
        __shared__ float we[HID];
        for (int i = tid; i < HID; i += 256) we[i] = wenc[i];
        __syncthreads();
        int warp = tid >> 5, lane = tid & 31;
        int row = blockIdx.x * 8 + warp;
        const float4* r4 = (const float4*)(Wf + (size_t)row*HID);
        float acc = 0.f;
#pragma unroll
        for (int t = 0; t < 4; t++) {
            float4 f = r4[lane + t*32];
            int c = (lane + t*32)*4;
            acc += f.x*we[c] + f.y*we[c+1] + f.z*we[c+2] + f.w*we[c+3];
        }
        for (int o = 16; o; o >>= 1) acc += __shfl_xor_sync(0xffffffffu, acc, o);
        if (lane == 0) g_venc[row] = acc;
    } else if (blockIdx.x < 640) {
        // transpose W (1024x512 f32) -> Wt (512x1024 bf16), 32x32 tiles
        __shared__ float ts[32][33];
        int t = blockIdx.x - 128;            // 512 tiles: 32 (k) x 16 (n)
        int k0 = (t & 31) * 32, n0 = (t >> 5) * 32;
        int tx = tid & 31, ty = tid >> 5;    // 32 x 8
#pragma unroll
        for (int r = 0; r < 4; r++) {
            int k = k0 + ty + r*8;
            ts[ty + r*8][tx] = Wf[(size_t)k*HID + n0 + tx];
        }
        __syncthreads();
#pragma unroll
        for (int r = 0; r < 4; r++) {
            int n = n0 + ty + r*8;
            g_Wt_bf[(size_t)n*IND + k0 + tx] = __float2bfloat16(ts[tx][ty + r*8]);
        }
    } else {
        // transpose Wk (512x512 f32) -> WkT[d][c], 32x32 tiles
        __shared__ float ts[32][33];
        int t = blockIdx.x - 640;            // 256 tiles: 16 (c) x 16 (d)
        int c0 = (t & 15) * 32, d0 = (t >> 4) * 32;
        int tx = tid & 31, ty = tid >> 5;
#pragma unroll
        for (int r = 0; r < 4; r++) {
            int c = c0 + ty + r*8;
            ts[ty + r*8][tx] = Wk[(size_t)c*HID + d0 + tx];
        }
        __syncthreads();
#pragma unroll
        for (int r = 0; r < 4; r++) {
            int d = d0 + ty + r*8;
            g_WkT[(size_t)d*HID + c0 + tx] = ts[tx][ty + r*8];
        }
    }
}

// ---------------- scores (fp32 GEMV) + inputs -> bf16, one pass -------------
__global__ void k_scores(const float* __restrict__ inp) {
    __shared__ float ve[IND];
    int tid = threadIdx.x;
    for (int i = tid; i < IND; i += 256) ve[i] = g_venc[i];
    __syncthreads();
    int warp = tid >> 5, lane = tid & 31;
    int row = blockIdx.x * 8 + warp;
    const float4* r4 = (const float4*)(inp + (size_t)row*IND);
    uint2* dst = (uint2*)(g_in_bf + (size_t)row*IND);
    float acc = 0.f;
#pragma unroll
    for (int t = 0; t < 8; t++) {
        int i = lane + t*32;
        float4 f = r4[i];
        int c = i*4;
        acc += f.x*ve[c] + f.y*ve[c+1] + f.z*ve[c+2] + f.w*ve[c+3];
        __nv_bfloat162 lo = __floats2bfloat162_rn(f.x, f.y);
        __nv_bfloat162 hi = __floats2bfloat162_rn(f.z, f.w);
        uint2 u;
        u.x = *reinterpret_cast<unsigned*>(&lo);
        u.y = *reinterpret_cast<unsigned*>(&hi);
        dst[i] = u;
    }
    for (int o = 16; o; o >>= 1) acc += __shfl_xor_sync(0xffffffffu, acc, o);
    if (lane == 0) g_scores[row] = acc;
}

// ---------------- fused top-16 (redundant per K-slice) + Q GEMV slice -------
__global__ void k_topkQ(const float* __restrict__ inp, const float* __restrict__ Wf) {
    __shared__ float sv[NN];
    __shared__ float wv[32];
    __shared__ int   wi[32];
    __shared__ int   ti[TOPK];
    __shared__ float s[128];
    __shared__ float p2[HID];
    int b = blockIdx.x, ks = blockIdx.y, tid = threadIdx.x;
    int lane = tid & 31, warp = tid >> 5;
    for (int i = tid; i < NN; i += 1024) sv[i] = g_scores[b*NN + i];
    __syncthreads();
    for (int k = 0; k < TOPK; k++) {
        float bvv = -FLT_MAX; int bi = 0x7fffffff;
#pragma unroll
        for (int t = 0; t < 8; t++) {
            int i = tid + t*1024;
            float v = sv[i];
            if (v > bvv || (v == bvv && i < bi)) { bvv = v; bi = i; }
        }
#pragma unroll
        for (int o = 16; o; o >>= 1) {
            float ov = __shfl_xor_sync(0xffffffffu, bvv, o);
            int   oi = __shfl_xor_sync(0xffffffffu, bi, o);
            if (ov > bvv || (ov == bvv && oi < bi)) { bvv = ov; bi = oi; }
        }
        if (lane == 0) { wv[warp] = bvv; wi[warp] = bi; }
        __syncthreads();
        if (warp == 0) {
            float v2 = wv[lane]; int i2 = wi[lane];
#pragma unroll
            for (int o = 16; o; o >>= 1) {
                float ov = __shfl_xor_sync(0xffffffffu, v2, o);
                int   oi = __shfl_xor_sync(0xffffffffu, i2, o);
                if (ov > v2 || (ov == v2 && oi < i2)) { v2 = ov; i2 = oi; }
            }
            if (lane == 0) { ti[k] = i2; sv[i2] = -FLT_MAX; }
        }
        __syncthreads();
    }
    if (tid < 128) {
        int k = ks*128 + tid;
        float acc = 0.f;
#pragma unroll
        for (int t = 0; t < TOPK; t++)
            acc += inp[((size_t)b*NN + ti[t])*IND + k];
        s[tid] = acc;
    }
    __syncthreads();
    int col = tid & 511, half = tid >> 9;
    float a = 0.f;
    int i0 = half*64;
#pragma unroll
    for (int i = 0; i < 64; i++)
        a += s[i0 + i]*Wf[(size_t)(ks*128 + i0 + i)*HID + col];
    if (half) p2[col] = a;
    __syncthreads();
    if (!half) atomicAdd(&g_Q[b*HID + col], (a + p2[col]) * (1.f/TOPK));
}

// ---------------- main GEMM: mma.sync, CTA 128x128, warp 32x64 --------------
__global__ __launch_bounds__(256, 2) void k_gemm(const float* __restrict__ bfeat) {
    __shared__ __align__(16) unsigned char raw[128*68*4];   // 34816 B
    __nv_bfloat16* As = (__nv_bfloat16*)raw;                // [128][64] swizzled
    __nv_bfloat16* Bs = (__nv_bfloat16*)(raw + 16384);      // [128][64] swizzled
    float (*Es)[68] = reinterpret_cast<float(*)[68]>(raw);

    int tid = threadIdx.x, wid = tid >> 5, lane = tid & 31;
    int m0 = blockIdx.y * 128, n0 = blockIdx.x * 128;
    int b = m0 >> 13;
    int wm = wid >> 1, wn = wid & 1;          // 4 x 2 warps, warp tile 32 x 64
    uint32_t As_u = smem_u32(As), Bs_u = smem_u32(Bs);

    const __nv_bfloat16* Ab = g_in_bf + (size_t)m0*IND;
    const __nv_bfloat16* Bb = g_Wt_bf + (size_t)n0*IND;

    int lrow = lane & 15, lcb = lane >> 4;
    float c[2][8][4] = {};

    for (int kt = 0; kt < 16; kt++) {
        int k0 = kt*64;
        __syncthreads();
#pragma unroll
        for (int i = 0; i < 4; i++) {              // A: 128x64 (1024 16B chunks)
            int id = tid + i*256;
            int row = id >> 3, c16 = id & 7;
            uint32_t bo = row*128 + c16*16;
            uint32_t sw = bo ^ ((row & 7) << 4);
            *(uint4*)((char*)As + sw) = *(const uint4*)(Ab + (size_t)row*IND + k0 + c16*8);
        }
#pragma unroll
        for (int i = 0; i < 4; i++) {              // B: 128x64 (1024 chunks)
            int id = tid + i*256;
            int row = id >> 3, c16 = id & 7;
            uint32_t bo = row*128 + c16*16;
            uint32_t sw = bo ^ ((row & 7) << 4);
            *(uint4*)((char*)Bs + sw) = *(const uint4*)(Bb + (size_t)row*IND + k0 + c16*8);
        }
        __syncthreads();
#pragma unroll
        for (int kk = 0; kk < 4; kk++) {
            int colb = kk*32 + lcb*16;
            uint32_t a[2][4];
#pragma unroll
            for (int i = 0; i < 2; i++) {
                int row = wm*32 + i*16 + lrow;
                uint32_t bo = row*128 + colb;
                ldm_x4(a[i][0], a[i][1], a[i][2], a[i][3],
                       As_u + (bo ^ ((row & 7) << 4)));
            }
            uint32_t bf[8][2];
#pragma unroll
            for (int j = 0; j < 4; j++) {
                int row = wn*64 + j*16 + lrow;
                uint32_t bo = row*128 + colb;
                uint32_t r0, r1, r2, r3;
                ldm_x4(r0, r1, r2, r3, Bs_u + (bo ^ ((row & 7) << 4)));
                bf[j*2][0] = r0; bf[j*2][1] = r2;
                bf[j*2+1][0] = r1; bf[j*2+1][1] = r3;
            }
#pragma unroll
            for (int i = 0; i < 2; i++)
#pragma unroll
                for (int nb = 0; nb < 8; nb++)
                    mma16816(c[i][nb], a[i][0], a[i][1], a[i][2], a[i][3],
                             bf[nb][0], bf[nb][1]);
        }
    }
    // two-phase epilogue (64 cols each), fused relu(x - Q), bf16 out
    int r4 = lane >> 2, cp = (lane & 3)*2;
    int ccc = tid & 63, rb = tid >> 6;
#pragma unroll
    for (int p = 0; p < 2; p++) {
        __syncthreads();
        if (wn == p) {
#pragma unroll
            for (int i = 0; i < 2; i++)
#pragma unroll
                for (int nb = 0; nb < 8; nb++) {
                    int rr = wm*32 + i*16 + r4;
                    int cc = nb*8 + cp;
                    Es[rr][cc]     = c[i][nb][0];
                    Es[rr][cc+1]   = c[i][nb][1];
                    Es[rr+8][cc]   = c[i][nb][2];
                    Es[rr+8][cc+1] = c[i][nb][3];
                }
        }
        __syncthreads();
        int col = n0 + p*64 + ccc;
        float qval = bfeat[col] - g_Q[b*HID + col];
#pragma unroll
        for (int t = 0; t < 32; t++) {
            int r = rb + t*4;
            g_x[(size_t)(m0 + r)*HID + col] =
                __float2bfloat16(fmaxf(Es[r][ccc] + qval, 0.f));
        }
    }
}

// ---------------- depthwise 3x3 conv (bf16 in, bf16 out) + cls row ----------
__global__ void k_conv(const float* __restrict__ cw, const float* __restrict__ cb,
                       const float* __restrict__ cls) {
    __shared__ float cws[HID*9];
    __shared__ float cbs[HID];
    int tid = threadIdx.x;   // 512 = channel
    int b = blockIdx.y;
#pragma unroll
    for (int k = 0; k < 9; k++) cws[tid*9 + k] = cw[tid*9 + k];
    cbs[tid] = cb[tid];
    if (blockIdx.x == 0)     // cls token row
        g_x2[(size_t)b*NP*HID + tid] = __float2bfloat16(cls[tid]);
    __syncthreads();
    int p0 = blockIdx.x * 16;
    for (int i = 0; i < 16; i++) {
        int p = p0 + i;
        if (p >= PP) break;
        int y = p / HH, x = p - y*HH;
        float acc = 0.f, center = 0.f;
#pragma unroll
        for (int dy = -1; dy <= 1; dy++) {
            int yy = y + dy; if (yy < 0 || yy >= HH) continue;
#pragma unroll
            for (int dx = -1; dx <= 1; dx++) {
                int xx = x + dx; if (xx < 0 || xx >= HH) continue;
                int pp2 = yy*HH + xx;
                int r = (pp2 < NN) ? pp2 : pp2 - NN;   // wrap padding rows
                float v = __bfloat162float(g_x[((size_t)(b*NN + r))*HID + tid]);
                acc += v * cws[tid*9 + (dy+1)*3 + (dx+1)];
                if (dy == 0 && dx == 0) center = v;
            }
        }
        g_x2[((size_t)b*NP + 1 + p)*HID + tid] = __float2bfloat16(acc + cbs[tid] + center);
    }
}

// ---------------- q projection: qvec += Q @ Wq (K-split x4, atomics) --------
__global__ void k_qproj(const float* __restrict__ Wq) {
    __shared__ float qs[128];
    int b = blockIdx.x, ks = blockIdx.y, tid = threadIdx.x;  // 512
    if (tid < 128) qs[tid] = g_Q[b*HID + ks*128 + tid];
    __syncthreads();
    float acc = 0.f;
#pragma unroll 4
    for (int i = 0; i < 128; i++)
        acc += qs[i]*Wq[(size_t)(ks*128 + i)*HID + tid];
    atomicAdd(&g_qvec[b*HID + tid], acc);
}

// ---------------- per-head key vectors u (coalesced via WkT) ----------------
__global__ void k_uprep(const float* __restrict__ bk) {
    __shared__ float qh[64];
    __shared__ float red[64];
    int b = blockIdx.x, h = blockIdx.y, tid = threadIdx.x;  // 512
    if (tid < 64) qh[tid] = g_qvec[b*HID + h*64 + tid];
    __syncthreads();
    float u = 0.f;
#pragma unroll 8
    for (int d = 0; d < 64; d++)
        u += qh[d]*g_WkT[(size_t)(h*64 + d)*HID + tid];
    g_u[(b*NHEAD + h)*HID + tid] = u;
    if (tid < 64) red[tid] = bk[h*64 + tid]*qh[tid];
    __syncthreads();
    if (tid == 0) {
        float qb = 0.f;
#pragma unroll
        for (int d = 0; d < 64; d++) qb += red[d];
        g_qbk[b*NHEAD + h] = qb;
    }
}

// ---------------- logits over 8282 keys (bf16 x2, 8 heads per pass) ---------
__global__ void k_logits() {
    __shared__ float us[NHEAD*HID];
    __shared__ float qb[NHEAD];
    int tid = threadIdx.x;  // 256
    int b = blockIdx.y;
    for (int i = tid; i < NHEAD*HID; i += 256) us[i] = g_u[b*NHEAD*HID + i];
    if (tid < NHEAD) qb[tid] = g_qbk[b*NHEAD + tid];
    __syncthreads();
    int warp = tid >> 5, lane = tid & 31;
    const float RS = 0.0441941738241592f;   // 1/sqrt(512)
    for (int it = 0; it < 4; it++) {
        int n = blockIdx.x*32 + warp*4 + it;
        if (n >= NP) break;
        const uint4* row = (const uint4*)(g_x2 + ((size_t)b*NP + n)*HID);  // 64 x uint4
        float acc[NHEAD] = {0,0,0,0,0,0,0,0};
#pragma unroll
        for (int t = 0; t < 2; t++) {
            int i = lane + t*32;
            uint4 u4 = row[i];
            int c = i*8;
            float2 f0 = __bfloat1622float2(*reinterpret_cast<__nv_bfloat162*>(&u4.x));
            float2 f1 = __bfloat1622float2(*reinterpret_cast<__nv_bfloat162*>(&u4.y));
            float2 f2 = __bfloat1622float2(*reinterpret_cast<__nv_bfloat162*>(&u4.z));
            float2 f3 = __bfloat1622float2(*reinterpret_cast<__nv_bfloat162*>(&u4.w));
#pragma unroll
            for (int h = 0; h < NHEAD; h++) {
                const float* uh = us + h*HID + c;
                acc[h] += f0.x*uh[0] + f0.y*uh[1] + f1.x*uh[2] + f1.y*uh[3]
                        + f2.x*uh[4] + f2.y*uh[5] + f3.x*uh[6] + f3.y*uh[7];
            }
        }
#pragma unroll
        for (int h = 0; h < NHEAD; h++)
            for (int o = 16; o; o >>= 1) acc[h] += __shfl_xor_sync(0xffffffffu, acc[h], o);
        if (lane == 0) {
#pragma unroll
            for (int h = 0; h < NHEAD; h++)
                g_logits[((size_t)(b*NHEAD + h))*NP + n] = (acc[h] + qb[h]) * RS;
        }
    }
}

// ---------------- softmax stats (max, sumexp) per (b,h) ---------------------
__global__ void k_softmax() {
    __shared__ float red[256];
    int bh = blockIdx.x, tid = threadIdx.x;
    const float* l = g_logits + (size_t)bh*NP;
    float m = -3.4e38f;
    for (int i = tid; i < NP; i += 256) m = fmaxf(m, l[i]);
    red[tid] = m; __syncthreads();
    for (int s = 128; s; s >>= 1) { if (tid < s) red[tid] = fmaxf(red[tid], red[tid+s]); __syncthreads(); }
    m = red[0]; __syncthreads();
    float sum = 0.f;
    for (int i = tid; i < NP; i += 256) sum += expf(l[i] - m);
    red[tid] = sum; __syncthreads();
    for (int s = 128; s; s >>= 1) { if (tid < s) red[tid] += red[tid+s]; __syncthreads(); }
    if (tid == 0) { g_mx[bh] = m; g_sm[bh] = red[0]; }
}

// ---------------- weighted sums w[b,h,:] = sum_n A x2[n,:] (bf16 x2) --------
#define WCH 130
__global__ void k_wsum() {
    __shared__ float as[NHEAD*WCH];
    int tid = threadIdx.x;   // 512 = channel
    int b = blockIdx.y;
    int base = blockIdx.x * WCH;
    for (int idx = tid; idx < NHEAD*WCH; idx += 512) {
        int h = idx / WCH, i = idx - h*WCH;
        int n = base + i;
        float a = 0.f;
        if (n < NP) {
            int bh = b*NHEAD + h;
            a = expf(g_logits[(size_t)bh*NP + n] - g_mx[bh]) / g_sm[bh];
        }
        as[idx] = a;
    }
    __syncthreads();
    float w[NHEAD] = {0,0,0,0,0,0,0,0};
    for (int i = 0; i < WCH; i++) {
        int n = base + i;
        if (n >= NP) break;
        float v = __bfloat162float(g_x2[((size_t)b*NP + n)*HID + tid]);
#pragma unroll
        for (int h = 0; h < NHEAD; h++) w[h] += as[h*WCH + i]*v;
    }
#pragma unroll
    for (int h = 0; h < NHEAD; h++)
        atomicAdd(&g_w[(b*NHEAD + h)*HID + tid], w[h]);
}

// ---------------- fin1: Ov += w @ Wv (K-split x4, atomics) ------------------
__global__ void k_fin1(const float* __restrict__ Wv) {
    __shared__ float wsm[NHEAD][128];
    int b = blockIdx.x, ks = blockIdx.y, tid = threadIdx.x;  // 512
    for (int i = tid; i < NHEAD*128; i += 512)
        wsm[i >> 7][i & 127] = g_w[b*NHEAD*HID + (i >> 7)*HID + ks*128 + (i & 127)];
    __syncthreads();
    int h = tid >> 6;
    float acc = 0.f;
#pragma unroll 4
    for (int i = 0; i < 128; i++)
        acc += wsm[h][i]*Wv[(size_t)(ks*128 + i)*HID + tid];
    atomicAdd(&g_Ov[b*HID + tid], acc);
}

// ---------------- fin2: t2 += O @ Wo, O = Ov + qvec (K-split x4) ------------
__global__ void k_fin2(const float* __restrict__ Wo) {
    __shared__ float Os[128];
    int b = blockIdx.x, ks = blockIdx.y, tid = threadIdx.x;  // 512
    if (tid < 128)
        Os[tid] = g_Ov[b*HID + ks*128 + tid] + g_qvec[b*HID + ks*128 + tid];
    __syncthreads();
    float acc = 0.f;
#pragma unroll 4
    for (int i = 0; i < 128; i++)
        acc += Os[i]*Wo[(size_t)(ks*128 + i)*HID + tid];
    atomicAdd(&g_t2[b*HID + tid], acc);
}

// ---------------- fin3: out = (O + relu(t2)) @ Wc + bc ----------------------
__global__ void k_fin3(const float* __restrict__ Wc, const float* __restrict__ bc,
                       float* __restrict__ out) {
    __shared__ float red[HID];
    int b = blockIdx.x, tid = threadIdx.x;  // 512
    float Ov = g_Ov[b*HID + tid] + g_qvec[b*HID + tid]
             + fmaxf(g_t2[b*HID + tid], 0.f);
    for (int j = 0; j < NCLS; j++) {
        red[tid] = Ov*Wc[tid*NCLS + j];
        __syncthreads();
        for (int s = 256; s; s >>= 1) { if (tid < s) red[tid] += red[tid+s]; __syncthreads(); }
        if (tid == 0) out[b*NCLS + j] = red[0] + bc[j];
        __syncthreads();
    }
}

// ---------------------------------------------------------------------------
extern "C" void kernel_launch(void* const* d_in, const int* in_sizes, int n_in,
                              void* d_out, int out_size) {
    const float* inputs  = (const float*)d_in[0];
    const float* W_feat  = (const float*)d_in[1];
    const float* b_feat  = (const float*)d_in[2];
    const float* w_enc   = (const float*)d_in[3];
    // d_in[4] = b_enc: uniform shift before sigmoid -> does not affect top-k
    const float* cls_tok = (const float*)d_in[5];
    const float* conv_w  = (const float*)d_in[6];
    const float* conv_b  = (const float*)d_in[7];
    const float* Wq = (const float*)d_in[8];
    const float* bq = (const float*)d_in[9];
    const float* Wk = (const float*)d_in[10];
    const float* bk = (const float*)d_in[11];
    const float* Wv = (const float*)d_in[12];
    const float* bv = (const float*)d_in[13];
    const float* Wo = (const float*)d_in[14];
    const float* bo = (const float*)d_in[15];
    const float* Wc = (const float*)d_in[16];
    const float* bc = (const float*)d_in[17];
    float* out = (float*)d_out;

    k_prep  <<<128 + 512 + 256, 256>>>(W_feat, w_enc, b_feat, bq, bv, bo, Wk);
    k_scores<<<MM/8, 256>>>(inputs);
    k_topkQ <<<dim3(BB, 8), 1024>>>(inputs, W_feat);
    k_gemm  <<<dim3(HID/128, MM/128), 256>>>(b_feat);
    k_conv  <<<dim3((PP+15)/16, BB), 512>>>(conv_w, conv_b, cls_tok);
    k_qproj <<<dim3(BB, 4), 512>>>(Wq);
    k_uprep <<<dim3(BB, NHEAD), 512>>>(bk);
    k_logits<<<dim3((NP+31)/32, BB), 256>>>();
    k_softmax<<<BB*NHEAD, 256>>>();
    k_wsum  <<<dim3((NP+WCH-1)/WCH, BB), 512>>>();
    k_fin1  <<<dim3(BB, 4), 512>>>(Wv);
    k_fin2  <<<dim3(BB, 4), 512>>>(Wo);
    k_fin3  <<<BB, 512>>>(Wc, bc, out);
}